// round 12
// baseline (speedup 1.0000x reference)
#include <cuda_runtime.h>
#include <cuda_fp16.h>
#include <math.h>
#include <stdint.h>

#define D_IN       4096
#define NUM_HEADS  32
#define HEAD_DIM   128
#define NUM_KV     8
#define SEQ        2048

// -------- scratch (device globals; no allocation allowed) --------
__device__ __half g_qh [(size_t)SEQ * NUM_HEADS * HEAD_DIM];
__device__ __half g_kh [(size_t)SEQ * NUM_KV   * HEAD_DIM];
__device__ __half g_vh [(size_t)SEQ * NUM_KV   * HEAD_DIM];
__device__ __half g_ctxh[(size_t)SEQ * NUM_HEADS * HEAD_DIM];
__device__ __half g_xh [(size_t)SEQ * D_IN];
__device__ __half g_wqkvT[(size_t)6144 * D_IN];                 // [N][K] fp16
__device__ __half g_woT[(size_t)D_IN * (NUM_HEADS*HEAD_DIM)];   // [N][K]
__device__ float  g_rope[(size_t)SEQ * 64 * 2];                 // [tok][f]{cos,sin}

// ---------------- helpers ----------------
__device__ __forceinline__ uint32_t smem_u32(const void* p) {
    uint32_t a;
    asm("{ .reg .u64 t; cvta.to.shared.u64 t, %1; cvt.u32.u64 %0, t; }"
        : "=r"(a) : "l"(p));
    return a;
}
__device__ __forceinline__ void cp16(uint32_t d, const void* s) {
    asm volatile("cp.async.cg.shared.global [%0], [%1], 16;"
                 :: "r"(d), "l"(s) : "memory");
}
#define CP_COMMIT() asm volatile("cp.async.commit_group;" ::: "memory")
#define CP_WAIT1()  asm volatile("cp.async.wait_group 1;" ::: "memory")

__device__ __forceinline__ void mma16(float* c, const uint32_t* a,
                                      uint32_t b0, uint32_t b1) {
    asm volatile(
        "mma.sync.aligned.m16n8k16.row.col.f32.f16.f16.f32 "
        "{%0,%1,%2,%3},{%4,%5,%6,%7},{%8,%9},{%0,%1,%2,%3};\n"
        : "+f"(c[0]), "+f"(c[1]), "+f"(c[2]), "+f"(c[3])
        : "r"(a[0]), "r"(a[1]), "r"(a[2]), "r"(a[3]), "r"(b0), "r"(b1));
}
__device__ __forceinline__ void ldsm4(uint32_t addr, uint32_t& r0, uint32_t& r1,
                                      uint32_t& r2, uint32_t& r3) {
    asm volatile("ldmatrix.sync.aligned.m8n8.x4.shared.b16 {%0,%1,%2,%3}, [%4];"
                 : "=r"(r0), "=r"(r1), "=r"(r2), "=r"(r3) : "r"(addr));
}
__device__ __forceinline__ void ldsm4t(uint32_t addr, uint32_t& r0, uint32_t& r1,
                                       uint32_t& r2, uint32_t& r3) {
    asm volatile("ldmatrix.sync.aligned.m8n8.x4.trans.shared.b16 {%0,%1,%2,%3}, [%4];"
                 : "=r"(r0), "=r"(r1), "=r"(r2), "=r"(r3) : "r"(addr));
}
__device__ __forceinline__ uint32_t h2bits(__half2 h) {
    return *(uint32_t*)&h;
}

// =================================================================
// fp16 GEMM (best measured config): B transposed [N][K].
// BM=BN=128, BK=64, 256 thr (8 warps: 4M x 2N), 3-stage cp.async,
// ldsm4 frags, smem stride 72 halves, 2 CTAs/SM.
// MODE 0: fp32 out. MODE 1: fused QKV epilogue (RMSNorm+RoPE).
// =================================================================
#define GSTAGE_BYTES 36864
#define GEMM_SMEM (3 * GSTAGE_BYTES)

template<int MODE>
__global__ __launch_bounds__(256, 2) void gemm_f16(
    const __half* __restrict__ A, const __half* __restrict__ B,
    float* __restrict__ Cout,
    __half* __restrict__ Qout, __half* __restrict__ Kout, __half* __restrict__ Vout,
    const float* __restrict__ qsc, const float* __restrict__ ksc,
    const float* __restrict__ ropeT,
    int N, int K)
{
    extern __shared__ __half sh[];
    const uint32_t sb = smem_u32(sh);
    const int tid = threadIdx.x;
    const int lane = tid & 31, wid = tid >> 5;
    const int wm = wid & 3, wn = wid >> 2;
    const int lg = lane >> 2, lc = lane & 3;
    const int m0 = blockIdx.y * 128, n0 = blockIdx.x * 128;
    const int nsteps = K / 64;
    const int lrow = tid >> 3;
    const int lchk = tid & 7;

    const uint32_t a_off = (uint32_t)((wm * 32 + (lane & 15)) * 144 + (lane >> 4) * 16);
    const uint32_t b_off = (uint32_t)(18432 +
        (wn * 64 + (lane & 7) + ((lane >> 4) * 8)) * 144 + ((lane >> 3) & 1) * 16);

    float acc[2][8][4];
#pragma unroll
    for (int i = 0; i < 2; ++i)
#pragma unroll
        for (int j = 0; j < 8; ++j)
#pragma unroll
            for (int e = 0; e < 4; ++e) acc[i][j][e] = 0.f;

    const __half* Ag = A + (size_t)m0 * K;
    const __half* Bg = B + (size_t)n0 * K;

#define LOAD_STAGE(s, k0) do {                                            \
    uint32_t as_ = sb + (uint32_t)(s) * GSTAGE_BYTES;                     \
    uint32_t bs_ = as_ + 18432;                                           \
    _Pragma("unroll")                                                     \
    for (int j_ = 0; j_ < 4; ++j_) {                                      \
        int row_ = lrow + 32 * j_;                                        \
        cp16(as_ + row_ * 144 + lchk * 16,                                \
             Ag + (size_t)row_ * K + (k0) + lchk * 8);                    \
        cp16(bs_ + row_ * 144 + lchk * 16,                                \
             Bg + (size_t)row_ * K + (k0) + lchk * 8);                    \
    }                                                                     \
} while (0)

    LOAD_STAGE(0, 0);  CP_COMMIT();
    LOAD_STAGE(1, 64); CP_COMMIT();

    for (int s = 0; s < nsteps; ++s) {
        CP_WAIT1();
        __syncthreads();
        if (s + 2 < nsteps) {
            int sn = s + 2; int bufn = sn - (sn / 3) * 3;
            LOAD_STAGE(bufn, sn * 64);
        }
        CP_COMMIT();

        const int buf = s - (s / 3) * 3;
        const uint32_t st = sb + (uint32_t)buf * GSTAGE_BYTES;
#pragma unroll
        for (int ks = 0; ks < 4; ++ks) {
            uint32_t af[2][4];
            ldsm4(st + a_off + ks * 32,            af[0][0], af[0][1], af[0][2], af[0][3]);
            ldsm4(st + a_off + ks * 32 + 16 * 144, af[1][0], af[1][1], af[1][2], af[1][3]);
            uint32_t bf[8][2];
#pragma unroll
            for (int ntp = 0; ntp < 4; ++ntp) {
                uint32_t r0, r1, r2, r3;
                ldsm4(st + b_off + ks * 32 + ntp * 16 * 144, r0, r1, r2, r3);
                bf[2*ntp][0] = r0; bf[2*ntp][1] = r1;
                bf[2*ntp+1][0] = r2; bf[2*ntp+1][1] = r3;
            }
#pragma unroll
            for (int nt = 0; nt < 8; ++nt) {
                mma16(acc[0][nt], af[0], bf[nt][0], bf[nt][1]);
                mma16(acc[1][nt], af[1], bf[nt][0], bf[nt][1]);
            }
        }
    }
#undef LOAD_STAGE

    if (MODE == 0) {
#pragma unroll
        for (int mt = 0; mt < 2; ++mt)
#pragma unroll
            for (int nt = 0; nt < 8; ++nt) {
                int row = m0 + wm * 32 + mt * 16 + lg;
                int col = n0 + wn * 64 + nt * 8 + 2 * lc;
                *(float2*)&Cout[(size_t)row * N + col] =
                    make_float2(acc[mt][nt][0], acc[mt][nt][1]);
                *(float2*)&Cout[(size_t)(row + 8) * N + col] =
                    make_float2(acc[mt][nt][2], acc[mt][nt][3]);
            }
        return;
    }

    // ---------------- MODE 1: fused QKV epilogue ----------------
    if (n0 >= 5120) {
#pragma unroll
        for (int mt = 0; mt < 2; ++mt)
#pragma unroll
            for (int nt = 0; nt < 8; ++nt) {
                int row = m0 + wm * 32 + mt * 16 + lg;
                int col = n0 - 5120 + wn * 64 + nt * 8 + 2 * lc;
                *(__half2*)&Vout[(size_t)row * 1024 + col] =
                    __floats2half2_rn(acc[mt][nt][0], acc[mt][nt][1]);
                *(__half2*)&Vout[(size_t)(row + 8) * 1024 + col] =
                    __floats2half2_rn(acc[mt][nt][2], acc[mt][nt][3]);
            }
        return;
    }

    const bool isQ = (n0 < 4096);
    const float* sc = isQ ? qsc : ksc;
    float* ssb = (float*)sh;          // [2][128]
    float* epi = (float*)sh + 256;    // [128][132]

    __syncthreads();

#pragma unroll
    for (int mt = 0; mt < 2; ++mt) {
        float s0 = 0.f, s1 = 0.f;
#pragma unroll
        for (int nt = 0; nt < 8; ++nt) {
            s0 += acc[mt][nt][0]*acc[mt][nt][0] + acc[mt][nt][1]*acc[mt][nt][1];
            s1 += acc[mt][nt][2]*acc[mt][nt][2] + acc[mt][nt][3]*acc[mt][nt][3];
        }
        s0 += __shfl_xor_sync(0xffffffffu, s0, 1);
        s0 += __shfl_xor_sync(0xffffffffu, s0, 2);
        s1 += __shfl_xor_sync(0xffffffffu, s1, 1);
        s1 += __shfl_xor_sync(0xffffffffu, s1, 2);
        if (lc == 0) {
            int r = wm * 32 + mt * 16 + lg;
            ssb[wn * 128 + r]     = s0;
            ssb[wn * 128 + r + 8] = s1;
        }
    }
    __syncthreads();

#pragma unroll
    for (int mt = 0; mt < 2; ++mt) {
        int r0 = wm * 32 + mt * 16 + lg;
        float rs0 = rsqrtf((ssb[r0]     + ssb[128 + r0])     * (1.f/128.f) + 1e-6f);
        float rs1 = rsqrtf((ssb[r0 + 8] + ssb[128 + r0 + 8]) * (1.f/128.f) + 1e-6f);
#pragma unroll
        for (int nt = 0; nt < 8; ++nt) {
            int c0 = wn * 64 + nt * 8 + 2 * lc;
            float2 scv = *(const float2*)&sc[c0];
            *(float2*)&epi[r0 * 132 + c0] =
                make_float2(acc[mt][nt][0] * rs0 * scv.x, acc[mt][nt][1] * rs0 * scv.y);
            *(float2*)&epi[(r0 + 8) * 132 + c0] =
                make_float2(acc[mt][nt][2] * rs1 * scv.x, acc[mt][nt][3] * rs1 * scv.y);
        }
    }
    __syncthreads();

    const int head = isQ ? (n0 >> 7) : ((n0 - 4096) >> 7);
    const int hstride = isQ ? NUM_HEADS : NUM_KV;
    __half* outp = isQ ? Qout : Kout;
#pragma unroll
    for (int mt = 0; mt < 2; ++mt) {
#pragma unroll
        for (int nt = 0; nt < 8; ++nt) {
            int r0 = wm * 32 + mt * 16 + lg;
            int c0 = wn * 64 + nt * 8 + 2 * lc;
            int cf = c0 & 63;
            float sgn = (c0 < 64) ? -1.f : 1.f;
#pragma unroll
            for (int hr = 0; hr < 2; ++hr) {
                int r = r0 + hr * 8;
                int tok = m0 + r;
                float4 tb = *(const float4*)&ropeT[(size_t)(tok * 64 + cf) * 2];
                float2 v = *(const float2*)&epi[r * 132 + c0];
                float2 p = *(const float2*)&epi[r * 132 + (c0 ^ 64)];
                float o0 = fmaf(v.x, tb.x, sgn * p.x * tb.y);
                float o1 = fmaf(v.y, tb.z, sgn * p.y * tb.w);
                *(__half2*)&outp[((size_t)tok * hstride + head) * 128 + c0] =
                    __floats2half2_rn(o0, o1);
            }
        }
    }
}

// =================================================================
// merged pre-pass (unchanged from R11)
// =================================================================
__global__ __launch_bounds__(256) void prepass_all_kernel(
    const float* __restrict__ Wq, const float* __restrict__ Wk,
    const float* __restrict__ Wv, const float* __restrict__ Wo,
    const float* __restrict__ x, const int* __restrict__ positions,
    __half* __restrict__ wqkvT, __half* __restrict__ woT,
    __half* __restrict__ xh, float* __restrict__ ropeT)
{
    const int tid = threadIdx.x;
    int b = blockIdx.x;

    if (b >= 11264) {
        int idx = (b - 11264) * 256 + tid;
        int tok = idx >> 6, f = idx & 63;
        double invf = exp2(-(double)f * (13.287712379549449 / 64.0));
        double ang  = (double)positions[tok] * invf;
        const double twopi = 6.283185307179586476925287;
        ang -= twopi * floor(ang / twopi);
        float c, s;
        sincosf((float)ang, &s, &c);
        ropeT[(size_t)idx * 2]     = c;
        ropeT[(size_t)idx * 2 + 1] = s;
        return;
    }
    if (b >= 10240) {
        const int n4 = (SEQ * D_IN) / 4;
        int i = (b - 10240) * 256 + tid;
        const int stride = 1024 * 256;
        for (; i < n4; i += stride) {
            float4 v = ((const float4*)x)[i];
            __half2 h0 = __floats2half2_rn(v.x, v.y);
            __half2 h1 = __floats2half2_rn(v.z, v.w);
            ((uint2*)xh)[i] = make_uint2(h2bits(h0), h2bits(h1));
        }
        return;
    }

    __shared__ float s[64][65];
    const float* W;
    __half* WT;
    int K, N, bx, by;
    if (b < 4096) {
        W = Wq; WT = wqkvT; K = D_IN; N = 4096;
        bx = b & 63; by = b >> 6;
    } else if (b < 5120) {
        b -= 4096;
        W = Wk; WT = wqkvT + (size_t)4096 * D_IN; K = D_IN; N = 1024;
        bx = b & 15; by = b >> 4;
    } else if (b < 6144) {
        b -= 5120;
        W = Wv; WT = wqkvT + (size_t)5120 * D_IN; K = D_IN; N = 1024;
        bx = b & 15; by = b >> 4;
    } else {
        b -= 6144;
        W = Wo; WT = woT; K = 4096; N = D_IN;
        bx = b & 63; by = b >> 6;
    }
    const int k0 = by * 64;
    const int n0 = bx * 64;
    const int rk = tid >> 4;
    const int cn = tid & 15;
#pragma unroll
    for (int it = 0; it < 4; ++it) {
        int k = rk + it * 16;
        float4 v = *(const float4*)&W[(size_t)(k0 + k) * N + n0 + cn * 4];
        s[k][cn*4+0] = v.x; s[k][cn*4+1] = v.y;
        s[k][cn*4+2] = v.z; s[k][cn*4+3] = v.w;
    }
    __syncthreads();
    const int rn = tid >> 3;
    const int ck = tid & 7;
#pragma unroll
    for (int it = 0; it < 2; ++it) {
        int n = rn + it * 32;
        __half h[8];
#pragma unroll
        for (int i = 0; i < 8; ++i) h[i] = __float2half_rn(s[ck*8+i][n]);
        *(uint4*)&WT[(size_t)(n0 + n) * K + k0 + ck * 8] = *(uint4*)h;
    }
}

// =================================================================
// Flash attention fp16 — now 2 CTAs/SM (2 x 104448 B smem fits).
// =================================================================
#define FST 136
#define FO_Q  0
#define FO_K0 17408
#define FO_K1 26112
#define FO_V0 34816
#define FO_V1 43520
#define FLASH_SMEM (52224 * 2)

__global__ __launch_bounds__(256, 2) void flash_f16_kernel(
    const __half* __restrict__ Qh, const __half* __restrict__ Kh,
    const __half* __restrict__ Vh, __half* __restrict__ Oh)
{
    extern __shared__ __half fsm[];
    const uint32_t sb = smem_u32(fsm);
    __half* Qs = fsm + FO_Q;

    const int tid  = threadIdx.x;
    const int lane = tid & 31;
    const int w    = tid >> 5;
    const int lg   = lane >> 2;
    const int lc   = lane & 3;
    const int h    = blockIdx.y;
    const int kvh  = h >> 2;
    const int qt   = gridDim.x - 1 - blockIdx.x;
    const int m0   = qt * 128;
    const int ntmax = 2 * qt + 1;
    const float softscale = 0.08838834764831845f;

    const int ctok = tid >> 4;
    const int cu   = tid & 15;

    const int m_sel = lane >> 3;
    const int r_sel = lane & 7;
    const uint32_t q_lane = sb + (uint32_t)((w * 16 + (m_sel & 1) * 8 + r_sel) * 272
                                            + (m_sel >> 1) * 16);
    const uint32_t k_lane_off = (uint32_t)(((m_sel >> 1) * 8 + r_sel) * 272
                                           + (m_sel & 1) * 16);
    const uint32_t v_lane_off = (uint32_t)(((m_sel & 1) * 8 + r_sel) * 272
                                           + (m_sel >> 1) * 16);

    {
        uint32_t kd = sb + FO_K0 * 2;
        uint32_t vd = sb + FO_V0 * 2;
#pragma unroll
        for (int it = 0; it < 4; ++it) {
            int tok = ctok + it * 16;
            cp16(kd + tok * 272 + cu * 16,
                 Kh + ((size_t)tok * NUM_KV + kvh) * HEAD_DIM + cu * 8);
            cp16(vd + tok * 272 + cu * 16,
                 Vh + ((size_t)tok * NUM_KV + kvh) * HEAD_DIM + cu * 8);
        }
        CP_COMMIT();
    }

#pragma unroll
    for (int it = 0; it < 8; ++it) {
        int id  = tid + it * 256;
        int tok = id >> 4;
        int u   = id & 15;
        *(uint4*)&Qs[tok * FST + u * 8] =
            *(const uint4*)&Qh[((size_t)(m0 + tok) * NUM_HEADS + h) * HEAD_DIM + u * 8];
    }

    float o[16][4];
#pragma unroll
    for (int dt = 0; dt < 16; ++dt)
#pragma unroll
        for (int e = 0; e < 4; ++e) o[dt][e] = 0.f;
    float mrun[2] = {-1e30f, -1e30f};
    float lrun[2] = {0.f, 0.f};

    for (int nt = 0; nt <= ntmax; ++nt) {
        const int n0 = nt * 64;
        const uint32_t vbuf = sb + (((nt & 1) ? FO_V1 : FO_V0)) * 2;
        const uint32_t kbuf = sb + (((nt & 1) ? FO_K1 : FO_K0)) * 2;

        __syncthreads();
        if (nt + 1 <= ntmax) {
            const int pn0 = (nt + 1) * 64;
            uint32_t kd = sb + ((((nt + 1) & 1) ? FO_K1 : FO_K0)) * 2;
            uint32_t vd = sb + ((((nt + 1) & 1) ? FO_V1 : FO_V0)) * 2;
#pragma unroll
            for (int it = 0; it < 4; ++it) {
                int tok = ctok + it * 16;
                cp16(kd + tok * 272 + cu * 16,
                     Kh + ((size_t)(pn0 + tok) * NUM_KV + kvh) * HEAD_DIM + cu * 8);
                cp16(vd + tok * 272 + cu * 16,
                     Vh + ((size_t)(pn0 + tok) * NUM_KV + kvh) * HEAD_DIM + cu * 8);
            }
        }
        CP_COMMIT();
        CP_WAIT1();
        __syncthreads();

        float s[8][4];
#pragma unroll
        for (int n = 0; n < 8; ++n)
#pragma unroll
            for (int e = 0; e < 4; ++e) s[n][e] = 0.f;

        const uint32_t k_lane = kbuf + k_lane_off;
#pragma unroll
        for (int ks = 0; ks < 8; ++ks) {
            uint32_t af[4];
            ldsm4(q_lane + ks * 32, af[0], af[1], af[2], af[3]);
#pragma unroll
            for (int np = 0; np < 4; ++np) {
                uint32_t r0, r1, r2, r3;
                ldsm4(k_lane + np * 16 * 272 + ks * 32, r0, r1, r2, r3);
                mma16(s[2*np],   af, r0, r1);
                mma16(s[2*np+1], af, r2, r3);
            }
        }

        const bool diag = (nt >= 2 * qt);
        float pmax[2] = {-1e30f, -1e30f};
#pragma unroll
        for (int n = 0; n < 8; ++n) {
#pragma unroll
            for (int e = 0; e < 4; ++e) {
                float v = s[n][e] * softscale;
                if (diag) {
                    int row = m0 + w * 16 + lg + (e >> 1) * 8;
                    int col = n0 + n * 8 + 2 * lc + (e & 1);
                    if (col > row) v = -1e30f;
                }
                s[n][e] = v;
                pmax[e >> 1] = fmaxf(pmax[e >> 1], v);
            }
        }
#pragma unroll
        for (int half = 0; half < 2; ++half) {
            pmax[half] = fmaxf(pmax[half], __shfl_xor_sync(0xffffffffu, pmax[half], 1));
            pmax[half] = fmaxf(pmax[half], __shfl_xor_sync(0xffffffffu, pmax[half], 2));
        }
        float alpha[2];
#pragma unroll
        for (int half = 0; half < 2; ++half) {
            float nm = fmaxf(mrun[half], pmax[half]);
            alpha[half] = __expf(mrun[half] - nm);
            mrun[half] = nm;
            lrun[half] *= alpha[half];
        }
#pragma unroll
        for (int dt = 0; dt < 16; ++dt) {
            o[dt][0] *= alpha[0]; o[dt][1] *= alpha[0];
            o[dt][2] *= alpha[1]; o[dt][3] *= alpha[1];
        }
        uint32_t pf[8][2];
        float lsum[2] = {0.f, 0.f};
#pragma unroll
        for (int n = 0; n < 8; ++n) {
            float p0 = __expf(s[n][0] - mrun[0]);
            float p1 = __expf(s[n][1] - mrun[0]);
            float p2 = __expf(s[n][2] - mrun[1]);
            float p3 = __expf(s[n][3] - mrun[1]);
            lsum[0] += p0 + p1;
            lsum[1] += p2 + p3;
            pf[n][0] = h2bits(__floats2half2_rn(p0, p1));
            pf[n][1] = h2bits(__floats2half2_rn(p2, p3));
        }
#pragma unroll
        for (int half = 0; half < 2; ++half) {
            lsum[half] += __shfl_xor_sync(0xffffffffu, lsum[half], 1);
            lsum[half] += __shfl_xor_sync(0xffffffffu, lsum[half], 2);
            lrun[half] += lsum[half];
        }

#pragma unroll
        for (int ks = 0; ks < 4; ++ks) {
            uint32_t af[4];
            af[0] = pf[2*ks][0];
            af[1] = pf[2*ks][1];
            af[2] = pf[2*ks+1][0];
            af[3] = pf[2*ks+1][1];
            uint32_t vbase = vbuf + (uint32_t)(ks * 16) * 272 + v_lane_off;
#pragma unroll
            for (int dtp = 0; dtp < 8; ++dtp) {
                uint32_t r0, r1, r2, r3;
                ldsm4t(vbase + dtp * 32, r0, r1, r2, r3);
                mma16(o[2*dtp],   af, r0, r1);
                mma16(o[2*dtp+1], af, r2, r3);
            }
        }
    }

    float inv0 = 1.f / lrun[0];
    float inv1 = 1.f / lrun[1];
#pragma unroll
    for (int dt = 0; dt < 16; ++dt) {
        int row = m0 + w * 16 + lg;
        int col = dt * 8 + 2 * lc;
        *(__half2*)&Oh[((size_t)row * NUM_HEADS + h) * HEAD_DIM + col] =
            __floats2half2_rn(o[dt][0] * inv0, o[dt][1] * inv0);
        *(__half2*)&Oh[((size_t)(row + 8) * NUM_HEADS + h) * HEAD_DIM + col] =
            __floats2half2_rn(o[dt][2] * inv1, o[dt][3] * inv1);
    }
}

// =================================================================
// kernel_launch  (4 launches)
// =================================================================
extern "C" void kernel_launch(void* const* d_in, const int* in_sizes, int n_in,
                              void* d_out, int out_size)
{
    const float* x   = (const float*)d_in[0];
    const int*   pos = (const int*)  d_in[1];
    const float* Wq  = (const float*)d_in[2];
    const float* Wk  = (const float*)d_in[3];
    const float* Wv  = (const float*)d_in[4];
    const float* Wo  = (const float*)d_in[5];
    const float* qsc = (const float*)d_in[6];
    const float* ksc = (const float*)d_in[7];
    float* out = (float*)d_out;

    __half *gqh, *gkh, *gvh, *gctxh, *gxh, *gwqkvT, *gwoT;
    float* grope;
    cudaGetSymbolAddress((void**)&gqh,    g_qh);
    cudaGetSymbolAddress((void**)&gkh,    g_kh);
    cudaGetSymbolAddress((void**)&gvh,    g_vh);
    cudaGetSymbolAddress((void**)&gctxh,  g_ctxh);
    cudaGetSymbolAddress((void**)&gxh,    g_xh);
    cudaGetSymbolAddress((void**)&gwqkvT, g_wqkvT);
    cudaGetSymbolAddress((void**)&gwoT,   g_woT);
    cudaGetSymbolAddress((void**)&grope,  g_rope);

    const int NQ = NUM_HEADS * HEAD_DIM;   // 4096

    cudaFuncSetAttribute(gemm_f16<0>,
                         cudaFuncAttributeMaxDynamicSharedMemorySize, GEMM_SMEM);
    cudaFuncSetAttribute(gemm_f16<1>,
                         cudaFuncAttributeMaxDynamicSharedMemorySize, GEMM_SMEM);
    cudaFuncSetAttribute(flash_f16_kernel,
                         cudaFuncAttributeMaxDynamicSharedMemorySize, FLASH_SMEM);

    // [0] merged pre-pass: transposes + x->fp16 + rope table
    prepass_all_kernel<<<11776, 256>>>(Wq, Wk, Wv, Wo, x, pos,
                                       gwqkvT, gwoT, gxh, grope);
    // [1] fused QKV projection + RMSNorm + RoPE
    gemm_f16<1><<<dim3(6144 / 128, SEQ / 128), 256, GEMM_SMEM>>>(
        gxh, gwqkvT, nullptr, gqh, gkh, gvh, qsc, ksc, grope, 6144, D_IN);
    // [2] flash attention (2 CTAs/SM)
    flash_f16_kernel<<<dim3(SEQ / 128, NUM_HEADS), 256, FLASH_SMEM>>>(
        gqh, gkh, gvh, gctxh);
    // [3] output projection
    gemm_f16<0><<<dim3(D_IN / 128, SEQ / 128), 256, GEMM_SMEM>>>(
        gctxh, gwoT, out, nullptr, nullptr, nullptr, nullptr, nullptr, nullptr,
        D_IN, NQ);
}

// round 13
// speedup vs baseline: 1.0036x; 1.0036x over previous
#include <cuda_runtime.h>
#include <cuda_fp16.h>
#include <math.h>
#include <stdint.h>

#define D_IN       4096
#define NUM_HEADS  32
#define HEAD_DIM   128
#define NUM_KV     8
#define SEQ        2048

// -------- scratch (device globals; no allocation allowed) --------
__device__ __half g_qh [(size_t)SEQ * NUM_HEADS * HEAD_DIM];
__device__ __half g_kh [(size_t)SEQ * NUM_KV   * HEAD_DIM];
__device__ __half g_vh [(size_t)SEQ * NUM_KV   * HEAD_DIM];
__device__ __half g_ctxh[(size_t)SEQ * NUM_HEADS * HEAD_DIM];
__device__ __half g_xh [(size_t)SEQ * D_IN];
__device__ __half g_wqkvT[(size_t)6144 * D_IN];                 // [N][K] fp16
__device__ __half g_woT[(size_t)D_IN * (NUM_HEADS*HEAD_DIM)];   // [N][K]
__device__ float  g_rope[(size_t)SEQ * 64 * 2];                 // [tok][f]{cos,sin}

// ---------------- helpers ----------------
__device__ __forceinline__ uint32_t smem_u32(const void* p) {
    uint32_t a;
    asm("{ .reg .u64 t; cvta.to.shared.u64 t, %1; cvt.u32.u64 %0, t; }"
        : "=r"(a) : "l"(p));
    return a;
}
__device__ __forceinline__ void cp16(uint32_t d, const void* s) {
    asm volatile("cp.async.cg.shared.global [%0], [%1], 16;"
                 :: "r"(d), "l"(s) : "memory");
}
#define CP_COMMIT() asm volatile("cp.async.commit_group;" ::: "memory")
#define CP_WAIT1()  asm volatile("cp.async.wait_group 1;" ::: "memory")
#define CP_WAIT0()  asm volatile("cp.async.wait_group 0;" ::: "memory")

__device__ __forceinline__ void mma16(float* c, const uint32_t* a,
                                      uint32_t b0, uint32_t b1) {
    asm volatile(
        "mma.sync.aligned.m16n8k16.row.col.f32.f16.f16.f32 "
        "{%0,%1,%2,%3},{%4,%5,%6,%7},{%8,%9},{%0,%1,%2,%3};\n"
        : "+f"(c[0]), "+f"(c[1]), "+f"(c[2]), "+f"(c[3])
        : "r"(a[0]), "r"(a[1]), "r"(a[2]), "r"(a[3]), "r"(b0), "r"(b1));
}
__device__ __forceinline__ void ldsm4(uint32_t addr, uint32_t& r0, uint32_t& r1,
                                      uint32_t& r2, uint32_t& r3) {
    asm volatile("ldmatrix.sync.aligned.m8n8.x4.shared.b16 {%0,%1,%2,%3}, [%4];"
                 : "=r"(r0), "=r"(r1), "=r"(r2), "=r"(r3) : "r"(addr));
}
__device__ __forceinline__ void ldsm4t(uint32_t addr, uint32_t& r0, uint32_t& r1,
                                       uint32_t& r2, uint32_t& r3) {
    asm volatile("ldmatrix.sync.aligned.m8n8.x4.trans.shared.b16 {%0,%1,%2,%3}, [%4];"
                 : "=r"(r0), "=r"(r1), "=r"(r2), "=r"(r3) : "r"(addr));
}
__device__ __forceinline__ uint32_t h2bits(__half2 h) {
    return *(uint32_t*)&h;
}

// =================================================================
// fp16 GEMM, PERSISTENT CTAs: grid = 296 (2/SM x 148), each CTA
// loops over linear tile ids. B transposed [N][K]. BM=BN=128,
// BK=64, 256 thr (8 warps: 4M x 2N), 3-stage cp.async, ldsm4 frags.
// MODE 0: fp32 out. MODE 1: fused QKV epilogue (RMSNorm+RoPE).
// =================================================================
#define GSTAGE_BYTES 36864
#define GEMM_SMEM (3 * GSTAGE_BYTES)
#define GEMM_GRID 296

template<int MODE>
__global__ __launch_bounds__(256, 2) void gemm_f16(
    const __half* __restrict__ A, const __half* __restrict__ B,
    float* __restrict__ Cout,
    __half* __restrict__ Qout, __half* __restrict__ Kout, __half* __restrict__ Vout,
    const float* __restrict__ qsc, const float* __restrict__ ksc,
    const float* __restrict__ ropeT,
    int N, int K, int ntiles)
{
    extern __shared__ __half sh[];
    const uint32_t sb = smem_u32(sh);
    const int tid = threadIdx.x;
    const int lane = tid & 31, wid = tid >> 5;
    const int wm = wid & 3, wn = wid >> 2;
    const int lg = lane >> 2, lc = lane & 3;
    const int nsteps = K / 64;
    const int ntx = N >> 7;
    const int lrow = tid >> 3;
    const int lchk = tid & 7;

    const uint32_t a_off = (uint32_t)((wm * 32 + (lane & 15)) * 144 + (lane >> 4) * 16);
    const uint32_t b_off = (uint32_t)(18432 +
        (wn * 64 + (lane & 7) + ((lane >> 4) * 8)) * 144 + ((lane >> 3) & 1) * 16);

    for (int t = blockIdx.x; t < ntiles; t += GEMM_GRID) {
        const int m0 = (t / ntx) * 128;
        const int n0 = (t % ntx) * 128;

        float acc[2][8][4];
#pragma unroll
        for (int i = 0; i < 2; ++i)
#pragma unroll
            for (int j = 0; j < 8; ++j)
#pragma unroll
                for (int e = 0; e < 4; ++e) acc[i][j][e] = 0.f;

        const __half* Ag = A + (size_t)m0 * K;
        const __half* Bg = B + (size_t)n0 * K;

#define LOAD_STAGE(s, k0) do {                                            \
    uint32_t as_ = sb + (uint32_t)(s) * GSTAGE_BYTES;                     \
    uint32_t bs_ = as_ + 18432;                                           \
    _Pragma("unroll")                                                     \
    for (int j_ = 0; j_ < 4; ++j_) {                                      \
        int row_ = lrow + 32 * j_;                                        \
        cp16(as_ + row_ * 144 + lchk * 16,                                \
             Ag + (size_t)row_ * K + (k0) + lchk * 8);                    \
        cp16(bs_ + row_ * 144 + lchk * 16,                                \
             Bg + (size_t)row_ * K + (k0) + lchk * 8);                    \
    }                                                                     \
} while (0)

        LOAD_STAGE(0, 0);  CP_COMMIT();
        LOAD_STAGE(1, 64); CP_COMMIT();

        for (int s = 0; s < nsteps; ++s) {
            CP_WAIT1();
            __syncthreads();
            if (s + 2 < nsteps) {
                int sn = s + 2; int bufn = sn - (sn / 3) * 3;
                LOAD_STAGE(bufn, sn * 64);
            }
            CP_COMMIT();

            const int buf = s - (s / 3) * 3;
            const uint32_t st = sb + (uint32_t)buf * GSTAGE_BYTES;
#pragma unroll
            for (int ks = 0; ks < 4; ++ks) {
                uint32_t af[2][4];
                ldsm4(st + a_off + ks * 32,            af[0][0], af[0][1], af[0][2], af[0][3]);
                ldsm4(st + a_off + ks * 32 + 16 * 144, af[1][0], af[1][1], af[1][2], af[1][3]);
                uint32_t bf[8][2];
#pragma unroll
                for (int ntp = 0; ntp < 4; ++ntp) {
                    uint32_t r0, r1, r2, r3;
                    ldsm4(st + b_off + ks * 32 + ntp * 16 * 144, r0, r1, r2, r3);
                    bf[2*ntp][0] = r0; bf[2*ntp][1] = r1;
                    bf[2*ntp+1][0] = r2; bf[2*ntp+1][1] = r3;
                }
#pragma unroll
                for (int nt = 0; nt < 8; ++nt) {
                    mma16(acc[0][nt], af[0], bf[nt][0], bf[nt][1]);
                    mma16(acc[1][nt], af[1], bf[nt][0], bf[nt][1]);
                }
            }
        }
#undef LOAD_STAGE
        CP_WAIT0();   // drain trailing (empty) groups before smem reuse

        if (MODE == 0) {
#pragma unroll
            for (int mt = 0; mt < 2; ++mt)
#pragma unroll
                for (int nt = 0; nt < 8; ++nt) {
                    int row = m0 + wm * 32 + mt * 16 + lg;
                    int col = n0 + wn * 64 + nt * 8 + 2 * lc;
                    *(float2*)&Cout[(size_t)row * N + col] =
                        make_float2(acc[mt][nt][0], acc[mt][nt][1]);
                    *(float2*)&Cout[(size_t)(row + 8) * N + col] =
                        make_float2(acc[mt][nt][2], acc[mt][nt][3]);
                }
            __syncthreads();   // close tile before next LOAD_STAGE
            continue;
        }

        // ---------------- MODE 1: fused QKV epilogue ----------------
        if (n0 >= 5120) {
#pragma unroll
            for (int mt = 0; mt < 2; ++mt)
#pragma unroll
                for (int nt = 0; nt < 8; ++nt) {
                    int row = m0 + wm * 32 + mt * 16 + lg;
                    int col = n0 - 5120 + wn * 64 + nt * 8 + 2 * lc;
                    *(__half2*)&Vout[(size_t)row * 1024 + col] =
                        __floats2half2_rn(acc[mt][nt][0], acc[mt][nt][1]);
                    *(__half2*)&Vout[(size_t)(row + 8) * 1024 + col] =
                        __floats2half2_rn(acc[mt][nt][2], acc[mt][nt][3]);
                }
            __syncthreads();
            continue;
        }

        const bool isQ = (n0 < 4096);
        const float* sc = isQ ? qsc : ksc;
        float* ssb = (float*)sh;          // [2][128]
        float* epi = (float*)sh + 256;    // [128][132]

        __syncthreads();   // all smem pipeline reads done

#pragma unroll
        for (int mt = 0; mt < 2; ++mt) {
            float s0 = 0.f, s1 = 0.f;
#pragma unroll
            for (int nt = 0; nt < 8; ++nt) {
                s0 += acc[mt][nt][0]*acc[mt][nt][0] + acc[mt][nt][1]*acc[mt][nt][1];
                s1 += acc[mt][nt][2]*acc[mt][nt][2] + acc[mt][nt][3]*acc[mt][nt][3];
            }
            s0 += __shfl_xor_sync(0xffffffffu, s0, 1);
            s0 += __shfl_xor_sync(0xffffffffu, s0, 2);
            s1 += __shfl_xor_sync(0xffffffffu, s1, 1);
            s1 += __shfl_xor_sync(0xffffffffu, s1, 2);
            if (lc == 0) {
                int r = wm * 32 + mt * 16 + lg;
                ssb[wn * 128 + r]     = s0;
                ssb[wn * 128 + r + 8] = s1;
            }
        }
        __syncthreads();

#pragma unroll
        for (int mt = 0; mt < 2; ++mt) {
            int r0 = wm * 32 + mt * 16 + lg;
            float rs0 = rsqrtf((ssb[r0]     + ssb[128 + r0])     * (1.f/128.f) + 1e-6f);
            float rs1 = rsqrtf((ssb[r0 + 8] + ssb[128 + r0 + 8]) * (1.f/128.f) + 1e-6f);
#pragma unroll
            for (int nt = 0; nt < 8; ++nt) {
                int c0 = wn * 64 + nt * 8 + 2 * lc;
                float2 scv = *(const float2*)&sc[c0];
                *(float2*)&epi[r0 * 132 + c0] =
                    make_float2(acc[mt][nt][0] * rs0 * scv.x, acc[mt][nt][1] * rs0 * scv.y);
                *(float2*)&epi[(r0 + 8) * 132 + c0] =
                    make_float2(acc[mt][nt][2] * rs1 * scv.x, acc[mt][nt][3] * rs1 * scv.y);
            }
        }
        __syncthreads();

        const int head = isQ ? (n0 >> 7) : ((n0 - 4096) >> 7);
        const int hstride = isQ ? NUM_HEADS : NUM_KV;
        __half* outp = isQ ? Qout : Kout;
#pragma unroll
        for (int mt = 0; mt < 2; ++mt) {
#pragma unroll
            for (int nt = 0; nt < 8; ++nt) {
                int r0 = wm * 32 + mt * 16 + lg;
                int c0 = wn * 64 + nt * 8 + 2 * lc;
                int cf = c0 & 63;
                float sgn = (c0 < 64) ? -1.f : 1.f;
#pragma unroll
                for (int hr = 0; hr < 2; ++hr) {
                    int r = r0 + hr * 8;
                    int tok = m0 + r;
                    float4 tb = *(const float4*)&ropeT[(size_t)(tok * 64 + cf) * 2];
                    float2 v = *(const float2*)&epi[r * 132 + c0];
                    float2 p = *(const float2*)&epi[r * 132 + (c0 ^ 64)];
                    float o0 = fmaf(v.x, tb.x, sgn * p.x * tb.y);
                    float o1 = fmaf(v.y, tb.z, sgn * p.y * tb.w);
                    *(__half2*)&outp[((size_t)tok * hstride + head) * 128 + c0] =
                        __floats2half2_rn(o0, o1);
                }
            }
        }
        __syncthreads();   // epi reads complete before next tile's smem writes
    }
}

// =================================================================
// merged pre-pass (unchanged from R11)
// =================================================================
__global__ __launch_bounds__(256) void prepass_all_kernel(
    const float* __restrict__ Wq, const float* __restrict__ Wk,
    const float* __restrict__ Wv, const float* __restrict__ Wo,
    const float* __restrict__ x, const int* __restrict__ positions,
    __half* __restrict__ wqkvT, __half* __restrict__ woT,
    __half* __restrict__ xh, float* __restrict__ ropeT)
{
    const int tid = threadIdx.x;
    int b = blockIdx.x;

    if (b >= 11264) {
        int idx = (b - 11264) * 256 + tid;
        int tok = idx >> 6, f = idx & 63;
        double invf = exp2(-(double)f * (13.287712379549449 / 64.0));
        double ang  = (double)positions[tok] * invf;
        const double twopi = 6.283185307179586476925287;
        ang -= twopi * floor(ang / twopi);
        float c, s;
        sincosf((float)ang, &s, &c);
        ropeT[(size_t)idx * 2]     = c;
        ropeT[(size_t)idx * 2 + 1] = s;
        return;
    }
    if (b >= 10240) {
        const int n4 = (SEQ * D_IN) / 4;
        int i = (b - 10240) * 256 + tid;
        const int stride = 1024 * 256;
        for (; i < n4; i += stride) {
            float4 v = ((const float4*)x)[i];
            __half2 h0 = __floats2half2_rn(v.x, v.y);
            __half2 h1 = __floats2half2_rn(v.z, v.w);
            ((uint2*)xh)[i] = make_uint2(h2bits(h0), h2bits(h1));
        }
        return;
    }

    __shared__ float s[64][65];
    const float* W;
    __half* WT;
    int K, N, bx, by;
    if (b < 4096) {
        W = Wq; WT = wqkvT; K = D_IN; N = 4096;
        bx = b & 63; by = b >> 6;
    } else if (b < 5120) {
        b -= 4096;
        W = Wk; WT = wqkvT + (size_t)4096 * D_IN; K = D_IN; N = 1024;
        bx = b & 15; by = b >> 4;
    } else if (b < 6144) {
        b -= 5120;
        W = Wv; WT = wqkvT + (size_t)5120 * D_IN; K = D_IN; N = 1024;
        bx = b & 15; by = b >> 4;
    } else {
        b -= 6144;
        W = Wo; WT = woT; K = 4096; N = D_IN;
        bx = b & 63; by = b >> 6;
    }
    const int k0 = by * 64;
    const int n0 = bx * 64;
    const int rk = tid >> 4;
    const int cn = tid & 15;
#pragma unroll
    for (int it = 0; it < 4; ++it) {
        int k = rk + it * 16;
        float4 v = *(const float4*)&W[(size_t)(k0 + k) * N + n0 + cn * 4];
        s[k][cn*4+0] = v.x; s[k][cn*4+1] = v.y;
        s[k][cn*4+2] = v.z; s[k][cn*4+3] = v.w;
    }
    __syncthreads();
    const int rn = tid >> 3;
    const int ck = tid & 7;
#pragma unroll
    for (int it = 0; it < 2; ++it) {
        int n = rn + it * 32;
        __half h[8];
#pragma unroll
        for (int i = 0; i < 8; ++i) h[i] = __float2half_rn(s[ck*8+i][n]);
        *(uint4*)&WT[(size_t)(n0 + n) * K + k0 + ck * 8] = *(uint4*)h;
    }
}

// =================================================================
// Flash attention fp16 (R11 config: occ 1, x4.trans V path)
// =================================================================
#define FST 136
#define FO_Q  0
#define FO_K0 17408
#define FO_K1 26112
#define FO_V0 34816
#define FO_V1 43520
#define FLASH_SMEM (52224 * 2)

__global__ __launch_bounds__(256, 1) void flash_f16_kernel(
    const __half* __restrict__ Qh, const __half* __restrict__ Kh,
    const __half* __restrict__ Vh, __half* __restrict__ Oh)
{
    extern __shared__ __half fsm[];
    const uint32_t sb = smem_u32(fsm);
    __half* Qs = fsm + FO_Q;

    const int tid  = threadIdx.x;
    const int lane = tid & 31;
    const int w    = tid >> 5;
    const int lg   = lane >> 2;
    const int lc   = lane & 3;
    const int h    = blockIdx.y;
    const int kvh  = h >> 2;
    const int qt   = gridDim.x - 1 - blockIdx.x;
    const int m0   = qt * 128;
    const int ntmax = 2 * qt + 1;
    const float softscale = 0.08838834764831845f;

    const int ctok = tid >> 4;
    const int cu   = tid & 15;

    const int m_sel = lane >> 3;
    const int r_sel = lane & 7;
    const uint32_t q_lane = sb + (uint32_t)((w * 16 + (m_sel & 1) * 8 + r_sel) * 272
                                            + (m_sel >> 1) * 16);
    const uint32_t k_lane_off = (uint32_t)(((m_sel >> 1) * 8 + r_sel) * 272
                                           + (m_sel & 1) * 16);
    const uint32_t v_lane_off = (uint32_t)(((m_sel & 1) * 8 + r_sel) * 272
                                           + (m_sel >> 1) * 16);

    {
        uint32_t kd = sb + FO_K0 * 2;
        uint32_t vd = sb + FO_V0 * 2;
#pragma unroll
        for (int it = 0; it < 4; ++it) {
            int tok = ctok + it * 16;
            cp16(kd + tok * 272 + cu * 16,
                 Kh + ((size_t)tok * NUM_KV + kvh) * HEAD_DIM + cu * 8);
            cp16(vd + tok * 272 + cu * 16,
                 Vh + ((size_t)tok * NUM_KV + kvh) * HEAD_DIM + cu * 8);
        }
        CP_COMMIT();
    }

#pragma unroll
    for (int it = 0; it < 8; ++it) {
        int id  = tid + it * 256;
        int tok = id >> 4;
        int u   = id & 15;
        *(uint4*)&Qs[tok * FST + u * 8] =
            *(const uint4*)&Qh[((size_t)(m0 + tok) * NUM_HEADS + h) * HEAD_DIM + u * 8];
    }

    float o[16][4];
#pragma unroll
    for (int dt = 0; dt < 16; ++dt)
#pragma unroll
        for (int e = 0; e < 4; ++e) o[dt][e] = 0.f;
    float mrun[2] = {-1e30f, -1e30f};
    float lrun[2] = {0.f, 0.f};

    for (int nt = 0; nt <= ntmax; ++nt) {
        const int n0 = nt * 64;
        const uint32_t vbuf = sb + (((nt & 1) ? FO_V1 : FO_V0)) * 2;
        const uint32_t kbuf = sb + (((nt & 1) ? FO_K1 : FO_K0)) * 2;

        __syncthreads();
        if (nt + 1 <= ntmax) {
            const int pn0 = (nt + 1) * 64;
            uint32_t kd = sb + ((((nt + 1) & 1) ? FO_K1 : FO_K0)) * 2;
            uint32_t vd = sb + ((((nt + 1) & 1) ? FO_V1 : FO_V0)) * 2;
#pragma unroll
            for (int it = 0; it < 4; ++it) {
                int tok = ctok + it * 16;
                cp16(kd + tok * 272 + cu * 16,
                     Kh + ((size_t)(pn0 + tok) * NUM_KV + kvh) * HEAD_DIM + cu * 8);
                cp16(vd + tok * 272 + cu * 16,
                     Vh + ((size_t)(pn0 + tok) * NUM_KV + kvh) * HEAD_DIM + cu * 8);
            }
        }
        CP_COMMIT();
        CP_WAIT1();
        __syncthreads();

        float s[8][4];
#pragma unroll
        for (int n = 0; n < 8; ++n)
#pragma unroll
            for (int e = 0; e < 4; ++e) s[n][e] = 0.f;

        const uint32_t k_lane = kbuf + k_lane_off;
#pragma unroll
        for (int ks = 0; ks < 8; ++ks) {
            uint32_t af[4];
            ldsm4(q_lane + ks * 32, af[0], af[1], af[2], af[3]);
#pragma unroll
            for (int np = 0; np < 4; ++np) {
                uint32_t r0, r1, r2, r3;
                ldsm4(k_lane + np * 16 * 272 + ks * 32, r0, r1, r2, r3);
                mma16(s[2*np],   af, r0, r1);
                mma16(s[2*np+1], af, r2, r3);
            }
        }

        const bool diag = (nt >= 2 * qt);
        float pmax[2] = {-1e30f, -1e30f};
#pragma unroll
        for (int n = 0; n < 8; ++n) {
#pragma unroll
            for (int e = 0; e < 4; ++e) {
                float v = s[n][e] * softscale;
                if (diag) {
                    int row = m0 + w * 16 + lg + (e >> 1) * 8;
                    int col = n0 + n * 8 + 2 * lc + (e & 1);
                    if (col > row) v = -1e30f;
                }
                s[n][e] = v;
                pmax[e >> 1] = fmaxf(pmax[e >> 1], v);
            }
        }
#pragma unroll
        for (int half = 0; half < 2; ++half) {
            pmax[half] = fmaxf(pmax[half], __shfl_xor_sync(0xffffffffu, pmax[half], 1));
            pmax[half] = fmaxf(pmax[half], __shfl_xor_sync(0xffffffffu, pmax[half], 2));
        }
        float alpha[2];
#pragma unroll
        for (int half = 0; half < 2; ++half) {
            float nm = fmaxf(mrun[half], pmax[half]);
            alpha[half] = __expf(mrun[half] - nm);
            mrun[half] = nm;
            lrun[half] *= alpha[half];
        }
#pragma unroll
        for (int dt = 0; dt < 16; ++dt) {
            o[dt][0] *= alpha[0]; o[dt][1] *= alpha[0];
            o[dt][2] *= alpha[1]; o[dt][3] *= alpha[1];
        }
        uint32_t pf[8][2];
        float lsum[2] = {0.f, 0.f};
#pragma unroll
        for (int n = 0; n < 8; ++n) {
            float p0 = __expf(s[n][0] - mrun[0]);
            float p1 = __expf(s[n][1] - mrun[0]);
            float p2 = __expf(s[n][2] - mrun[1]);
            float p3 = __expf(s[n][3] - mrun[1]);
            lsum[0] += p0 + p1;
            lsum[1] += p2 + p3;
            pf[n][0] = h2bits(__floats2half2_rn(p0, p1));
            pf[n][1] = h2bits(__floats2half2_rn(p2, p3));
        }
#pragma unroll
        for (int half = 0; half < 2; ++half) {
            lsum[half] += __shfl_xor_sync(0xffffffffu, lsum[half], 1);
            lsum[half] += __shfl_xor_sync(0xffffffffu, lsum[half], 2);
            lrun[half] += lsum[half];
        }

#pragma unroll
        for (int ks = 0; ks < 4; ++ks) {
            uint32_t af[4];
            af[0] = pf[2*ks][0];
            af[1] = pf[2*ks][1];
            af[2] = pf[2*ks+1][0];
            af[3] = pf[2*ks+1][1];
            uint32_t vbase = vbuf + (uint32_t)(ks * 16) * 272 + v_lane_off;
#pragma unroll
            for (int dtp = 0; dtp < 8; ++dtp) {
                uint32_t r0, r1, r2, r3;
                ldsm4t(vbase + dtp * 32, r0, r1, r2, r3);
                mma16(o[2*dtp],   af, r0, r1);
                mma16(o[2*dtp+1], af, r2, r3);
            }
        }
    }

    float inv0 = 1.f / lrun[0];
    float inv1 = 1.f / lrun[1];
#pragma unroll
    for (int dt = 0; dt < 16; ++dt) {
        int row = m0 + w * 16 + lg;
        int col = dt * 8 + 2 * lc;
        *(__half2*)&Oh[((size_t)row * NUM_HEADS + h) * HEAD_DIM + col] =
            __floats2half2_rn(o[dt][0] * inv0, o[dt][1] * inv0);
        *(__half2*)&Oh[((size_t)(row + 8) * NUM_HEADS + h) * HEAD_DIM + col] =
            __floats2half2_rn(o[dt][2] * inv1, o[dt][3] * inv1);
    }
}

// =================================================================
// kernel_launch  (4 launches)
// =================================================================
extern "C" void kernel_launch(void* const* d_in, const int* in_sizes, int n_in,
                              void* d_out, int out_size)
{
    const float* x   = (const float*)d_in[0];
    const int*   pos = (const int*)  d_in[1];
    const float* Wq  = (const float*)d_in[2];
    const float* Wk  = (const float*)d_in[3];
    const float* Wv  = (const float*)d_in[4];
    const float* Wo  = (const float*)d_in[5];
    const float* qsc = (const float*)d_in[6];
    const float* ksc = (const float*)d_in[7];
    float* out = (float*)d_out;

    __half *gqh, *gkh, *gvh, *gctxh, *gxh, *gwqkvT, *gwoT;
    float* grope;
    cudaGetSymbolAddress((void**)&gqh,    g_qh);
    cudaGetSymbolAddress((void**)&gkh,    g_kh);
    cudaGetSymbolAddress((void**)&gvh,    g_vh);
    cudaGetSymbolAddress((void**)&gctxh,  g_ctxh);
    cudaGetSymbolAddress((void**)&gxh,    g_xh);
    cudaGetSymbolAddress((void**)&gwqkvT, g_wqkvT);
    cudaGetSymbolAddress((void**)&gwoT,   g_woT);
    cudaGetSymbolAddress((void**)&grope,  g_rope);

    const int NQ = NUM_HEADS * HEAD_DIM;   // 4096

    cudaFuncSetAttribute(gemm_f16<0>,
                         cudaFuncAttributeMaxDynamicSharedMemorySize, GEMM_SMEM);
    cudaFuncSetAttribute(gemm_f16<1>,
                         cudaFuncAttributeMaxDynamicSharedMemorySize, GEMM_SMEM);
    cudaFuncSetAttribute(flash_f16_kernel,
                         cudaFuncAttributeMaxDynamicSharedMemorySize, FLASH_SMEM);

    // [0] merged pre-pass: transposes + x->fp16 + rope table
    prepass_all_kernel<<<11776, 256>>>(Wq, Wk, Wv, Wo, x, pos,
                                       gwqkvT, gwoT, gxh, grope);
    // [1] fused QKV projection + RMSNorm + RoPE (persistent, 768 tiles)
    gemm_f16<1><<<GEMM_GRID, 256, GEMM_SMEM>>>(
        gxh, gwqkvT, nullptr, gqh, gkh, gvh, qsc, ksc, grope,
        6144, D_IN, (6144 / 128) * (SEQ / 128));
    // [2] flash attention (occ 1 — R11 config)
    flash_f16_kernel<<<dim3(SEQ / 128, NUM_HEADS), 256, FLASH_SMEM>>>(
        gqh, gkh, gvh, gctxh);
    // [3] output projection (persistent, 512 tiles)
    gemm_f16<0><<<GEMM_GRID, 256, GEMM_SMEM>>>(
        gctxh, gwoT, out, nullptr, nullptr, nullptr, nullptr, nullptr, nullptr,
        D_IN, NQ, (D_IN / 128) * (SEQ / 128));
}

// round 14
// speedup vs baseline: 1.0521x; 1.0483x over previous
#include <cuda_runtime.h>
#include <cuda_fp16.h>
#include <math.h>
#include <stdint.h>

#define D_IN       4096
#define NUM_HEADS  32
#define HEAD_DIM   128
#define NUM_KV     8
#define SEQ        2048

// -------- scratch (device globals; no allocation allowed) --------
__device__ __half g_qh [(size_t)SEQ * NUM_HEADS * HEAD_DIM];
__device__ __half g_kh [(size_t)SEQ * NUM_KV   * HEAD_DIM];
__device__ __half g_vh [(size_t)SEQ * NUM_KV   * HEAD_DIM];
__device__ __half g_ctxh[(size_t)SEQ * NUM_HEADS * HEAD_DIM];
__device__ __half g_xh [(size_t)SEQ * D_IN];
__device__ __half g_wqkvT[(size_t)6144 * D_IN];                 // [N][K] fp16
__device__ __half g_woT[(size_t)D_IN * (NUM_HEADS*HEAD_DIM)];   // [N][K]
__device__ float  g_rope[(size_t)SEQ * 64 * 2];                 // [tok][f]{cos,sin}

// ---------------- helpers ----------------
__device__ __forceinline__ uint32_t smem_u32(const void* p) {
    uint32_t a;
    asm("{ .reg .u64 t; cvta.to.shared.u64 t, %1; cvt.u32.u64 %0, t; }"
        : "=r"(a) : "l"(p));
    return a;
}
__device__ __forceinline__ void cp16(uint32_t d, const void* s) {
    asm volatile("cp.async.cg.shared.global [%0], [%1], 16;"
                 :: "r"(d), "l"(s) : "memory");
}
#define CP_COMMIT() asm volatile("cp.async.commit_group;" ::: "memory")
#define CP_WAIT1()  asm volatile("cp.async.wait_group 1;" ::: "memory")

__device__ __forceinline__ void mma16(float* c, const uint32_t* a,
                                      uint32_t b0, uint32_t b1) {
    asm volatile(
        "mma.sync.aligned.m16n8k16.row.col.f32.f16.f16.f32 "
        "{%0,%1,%2,%3},{%4,%5,%6,%7},{%8,%9},{%0,%1,%2,%3};\n"
        : "+f"(c[0]), "+f"(c[1]), "+f"(c[2]), "+f"(c[3])
        : "r"(a[0]), "r"(a[1]), "r"(a[2]), "r"(a[3]), "r"(b0), "r"(b1));
}
__device__ __forceinline__ void ldsm4(uint32_t addr, uint32_t& r0, uint32_t& r1,
                                      uint32_t& r2, uint32_t& r3) {
    asm volatile("ldmatrix.sync.aligned.m8n8.x4.shared.b16 {%0,%1,%2,%3}, [%4];"
                 : "=r"(r0), "=r"(r1), "=r"(r2), "=r"(r3) : "r"(addr));
}
__device__ __forceinline__ void ldsm4t(uint32_t addr, uint32_t& r0, uint32_t& r1,
                                       uint32_t& r2, uint32_t& r3) {
    asm volatile("ldmatrix.sync.aligned.m8n8.x4.trans.shared.b16 {%0,%1,%2,%3}, [%4];"
                 : "=r"(r0), "=r"(r1), "=r"(r2), "=r"(r3) : "r"(addr));
}
__device__ __forceinline__ uint32_t h2bits(__half2 h) {
    return *(uint32_t*)&h;
}

// =================================================================
// fp16 GEMM (R11 config — best measured): B transposed [N][K].
// BM=BN=128, BK=64, 256 thr (8 warps: 4M x 2N), 3-stage cp.async,
// ldsm4 frags, smem stride 72 halves, 2 CTAs/SM.
// MODE 0: fp32 out. MODE 1: fused QKV epilogue (RMSNorm+RoPE).
// softscale (1/sqrt(128)) is folded into Q's row scale here.
// =================================================================
#define GSTAGE_BYTES 36864
#define GEMM_SMEM (3 * GSTAGE_BYTES)

template<int MODE>
__global__ __launch_bounds__(256, 2) void gemm_f16(
    const __half* __restrict__ A, const __half* __restrict__ B,
    float* __restrict__ Cout,
    __half* __restrict__ Qout, __half* __restrict__ Kout, __half* __restrict__ Vout,
    const float* __restrict__ qsc, const float* __restrict__ ksc,
    const float* __restrict__ ropeT,
    int N, int K)
{
    extern __shared__ __half sh[];
    const uint32_t sb = smem_u32(sh);
    const int tid = threadIdx.x;
    const int lane = tid & 31, wid = tid >> 5;
    const int wm = wid & 3, wn = wid >> 2;
    const int lg = lane >> 2, lc = lane & 3;
    const int m0 = blockIdx.y * 128, n0 = blockIdx.x * 128;
    const int nsteps = K / 64;
    const int lrow = tid >> 3;
    const int lchk = tid & 7;

    const uint32_t a_off = (uint32_t)((wm * 32 + (lane & 15)) * 144 + (lane >> 4) * 16);
    const uint32_t b_off = (uint32_t)(18432 +
        (wn * 64 + (lane & 7) + ((lane >> 4) * 8)) * 144 + ((lane >> 3) & 1) * 16);

    float acc[2][8][4];
#pragma unroll
    for (int i = 0; i < 2; ++i)
#pragma unroll
        for (int j = 0; j < 8; ++j)
#pragma unroll
            for (int e = 0; e < 4; ++e) acc[i][j][e] = 0.f;

    const __half* Ag = A + (size_t)m0 * K;
    const __half* Bg = B + (size_t)n0 * K;

#define LOAD_STAGE(s, k0) do {                                            \
    uint32_t as_ = sb + (uint32_t)(s) * GSTAGE_BYTES;                     \
    uint32_t bs_ = as_ + 18432;                                           \
    _Pragma("unroll")                                                     \
    for (int j_ = 0; j_ < 4; ++j_) {                                      \
        int row_ = lrow + 32 * j_;                                        \
        cp16(as_ + row_ * 144 + lchk * 16,                                \
             Ag + (size_t)row_ * K + (k0) + lchk * 8);                    \
        cp16(bs_ + row_ * 144 + lchk * 16,                                \
             Bg + (size_t)row_ * K + (k0) + lchk * 8);                    \
    }                                                                     \
} while (0)

    LOAD_STAGE(0, 0);  CP_COMMIT();
    LOAD_STAGE(1, 64); CP_COMMIT();

    for (int s = 0; s < nsteps; ++s) {
        CP_WAIT1();
        __syncthreads();
        if (s + 2 < nsteps) {
            int sn = s + 2; int bufn = sn - (sn / 3) * 3;
            LOAD_STAGE(bufn, sn * 64);
        }
        CP_COMMIT();

        const int buf = s - (s / 3) * 3;
        const uint32_t st = sb + (uint32_t)buf * GSTAGE_BYTES;
#pragma unroll
        for (int ks = 0; ks < 4; ++ks) {
            uint32_t af[2][4];
            ldsm4(st + a_off + ks * 32,            af[0][0], af[0][1], af[0][2], af[0][3]);
            ldsm4(st + a_off + ks * 32 + 16 * 144, af[1][0], af[1][1], af[1][2], af[1][3]);
            uint32_t bf[8][2];
#pragma unroll
            for (int ntp = 0; ntp < 4; ++ntp) {
                uint32_t r0, r1, r2, r3;
                ldsm4(st + b_off + ks * 32 + ntp * 16 * 144, r0, r1, r2, r3);
                bf[2*ntp][0] = r0; bf[2*ntp][1] = r1;
                bf[2*ntp+1][0] = r2; bf[2*ntp+1][1] = r3;
            }
#pragma unroll
            for (int nt = 0; nt < 8; ++nt) {
                mma16(acc[0][nt], af[0], bf[nt][0], bf[nt][1]);
                mma16(acc[1][nt], af[1], bf[nt][0], bf[nt][1]);
            }
        }
    }
#undef LOAD_STAGE

    if (MODE == 0) {
#pragma unroll
        for (int mt = 0; mt < 2; ++mt)
#pragma unroll
            for (int nt = 0; nt < 8; ++nt) {
                int row = m0 + wm * 32 + mt * 16 + lg;
                int col = n0 + wn * 64 + nt * 8 + 2 * lc;
                *(float2*)&Cout[(size_t)row * N + col] =
                    make_float2(acc[mt][nt][0], acc[mt][nt][1]);
                *(float2*)&Cout[(size_t)(row + 8) * N + col] =
                    make_float2(acc[mt][nt][2], acc[mt][nt][3]);
            }
        return;
    }

    // ---------------- MODE 1: fused QKV epilogue ----------------
    if (n0 >= 5120) {
#pragma unroll
        for (int mt = 0; mt < 2; ++mt)
#pragma unroll
            for (int nt = 0; nt < 8; ++nt) {
                int row = m0 + wm * 32 + mt * 16 + lg;
                int col = n0 - 5120 + wn * 64 + nt * 8 + 2 * lc;
                *(__half2*)&Vout[(size_t)row * 1024 + col] =
                    __floats2half2_rn(acc[mt][nt][0], acc[mt][nt][1]);
                *(__half2*)&Vout[(size_t)(row + 8) * 1024 + col] =
                    __floats2half2_rn(acc[mt][nt][2], acc[mt][nt][3]);
            }
        return;
    }

    const bool isQ = (n0 < 4096);
    const float* sc = isQ ? qsc : ksc;
    const float postmul = isQ ? 0.08838834764831845f : 1.0f;  // softscale fold
    float* ssb = (float*)sh;          // [2][128]
    float* epi = (float*)sh + 256;    // [128][132]

    __syncthreads();

#pragma unroll
    for (int mt = 0; mt < 2; ++mt) {
        float s0 = 0.f, s1 = 0.f;
#pragma unroll
        for (int nt = 0; nt < 8; ++nt) {
            s0 += acc[mt][nt][0]*acc[mt][nt][0] + acc[mt][nt][1]*acc[mt][nt][1];
            s1 += acc[mt][nt][2]*acc[mt][nt][2] + acc[mt][nt][3]*acc[mt][nt][3];
        }
        s0 += __shfl_xor_sync(0xffffffffu, s0, 1);
        s0 += __shfl_xor_sync(0xffffffffu, s0, 2);
        s1 += __shfl_xor_sync(0xffffffffu, s1, 1);
        s1 += __shfl_xor_sync(0xffffffffu, s1, 2);
        if (lc == 0) {
            int r = wm * 32 + mt * 16 + lg;
            ssb[wn * 128 + r]     = s0;
            ssb[wn * 128 + r + 8] = s1;
        }
    }
    __syncthreads();

#pragma unroll
    for (int mt = 0; mt < 2; ++mt) {
        int r0 = wm * 32 + mt * 16 + lg;
        float rs0 = rsqrtf((ssb[r0]     + ssb[128 + r0])     * (1.f/128.f) + 1e-6f) * postmul;
        float rs1 = rsqrtf((ssb[r0 + 8] + ssb[128 + r0 + 8]) * (1.f/128.f) + 1e-6f) * postmul;
#pragma unroll
        for (int nt = 0; nt < 8; ++nt) {
            int c0 = wn * 64 + nt * 8 + 2 * lc;
            float2 scv = *(const float2*)&sc[c0];
            *(float2*)&epi[r0 * 132 + c0] =
                make_float2(acc[mt][nt][0] * rs0 * scv.x, acc[mt][nt][1] * rs0 * scv.y);
            *(float2*)&epi[(r0 + 8) * 132 + c0] =
                make_float2(acc[mt][nt][2] * rs1 * scv.x, acc[mt][nt][3] * rs1 * scv.y);
        }
    }
    __syncthreads();

    const int head = isQ ? (n0 >> 7) : ((n0 - 4096) >> 7);
    const int hstride = isQ ? NUM_HEADS : NUM_KV;
    __half* outp = isQ ? Qout : Kout;
#pragma unroll
    for (int mt = 0; mt < 2; ++mt) {
#pragma unroll
        for (int nt = 0; nt < 8; ++nt) {
            int r0 = wm * 32 + mt * 16 + lg;
            int c0 = wn * 64 + nt * 8 + 2 * lc;
            int cf = c0 & 63;
            float sgn = (c0 < 64) ? -1.f : 1.f;
#pragma unroll
            for (int hr = 0; hr < 2; ++hr) {
                int r = r0 + hr * 8;
                int tok = m0 + r;
                float4 tb = *(const float4*)&ropeT[(size_t)(tok * 64 + cf) * 2];
                float2 v = *(const float2*)&epi[r * 132 + c0];
                float2 p = *(const float2*)&epi[r * 132 + (c0 ^ 64)];
                float o0 = fmaf(v.x, tb.x, sgn * p.x * tb.y);
                float o1 = fmaf(v.y, tb.z, sgn * p.y * tb.w);
                *(__half2*)&outp[((size_t)tok * hstride + head) * 128 + c0] =
                    __floats2half2_rn(o0, o1);
            }
        }
    }
}

// =================================================================
// merged pre-pass (unchanged from R11)
// =================================================================
__global__ __launch_bounds__(256) void prepass_all_kernel(
    const float* __restrict__ Wq, const float* __restrict__ Wk,
    const float* __restrict__ Wv, const float* __restrict__ Wo,
    const float* __restrict__ x, const int* __restrict__ positions,
    __half* __restrict__ wqkvT, __half* __restrict__ woT,
    __half* __restrict__ xh, float* __restrict__ ropeT)
{
    const int tid = threadIdx.x;
    int b = blockIdx.x;

    if (b >= 11264) {
        int idx = (b - 11264) * 256 + tid;
        int tok = idx >> 6, f = idx & 63;
        double invf = exp2(-(double)f * (13.287712379549449 / 64.0));
        double ang  = (double)positions[tok] * invf;
        const double twopi = 6.283185307179586476925287;
        ang -= twopi * floor(ang / twopi);
        float c, s;
        sincosf((float)ang, &s, &c);
        ropeT[(size_t)idx * 2]     = c;
        ropeT[(size_t)idx * 2 + 1] = s;
        return;
    }
    if (b >= 10240) {
        const int n4 = (SEQ * D_IN) / 4;
        int i = (b - 10240) * 256 + tid;
        const int stride = 1024 * 256;
        for (; i < n4; i += stride) {
            float4 v = ((const float4*)x)[i];
            __half2 h0 = __floats2half2_rn(v.x, v.y);
            __half2 h1 = __floats2half2_rn(v.z, v.w);
            ((uint2*)xh)[i] = make_uint2(h2bits(h0), h2bits(h1));
        }
        return;
    }

    __shared__ float s[64][65];
    const float* W;
    __half* WT;
    int K, N, bx, by;
    if (b < 4096) {
        W = Wq; WT = wqkvT; K = D_IN; N = 4096;
        bx = b & 63; by = b >> 6;
    } else if (b < 5120) {
        b -= 4096;
        W = Wk; WT = wqkvT + (size_t)4096 * D_IN; K = D_IN; N = 1024;
        bx = b & 15; by = b >> 4;
    } else if (b < 6144) {
        b -= 5120;
        W = Wv; WT = wqkvT + (size_t)5120 * D_IN; K = D_IN; N = 1024;
        bx = b & 15; by = b >> 4;
    } else {
        b -= 6144;
        W = Wo; WT = woT; K = 4096; N = D_IN;
        bx = b & 63; by = b >> 6;
    }
    const int k0 = by * 64;
    const int n0 = bx * 64;
    const int rk = tid >> 4;
    const int cn = tid & 15;
#pragma unroll
    for (int it = 0; it < 4; ++it) {
        int k = rk + it * 16;
        float4 v = *(const float4*)&W[(size_t)(k0 + k) * N + n0 + cn * 4];
        s[k][cn*4+0] = v.x; s[k][cn*4+1] = v.y;
        s[k][cn*4+2] = v.z; s[k][cn*4+3] = v.w;
    }
    __syncthreads();
    const int rn = tid >> 3;
    const int ck = tid & 7;
#pragma unroll
    for (int it = 0; it < 2; ++it) {
        int n = rn + it * 32;
        __half h[8];
#pragma unroll
        for (int i = 0; i < 8; ++i) h[i] = __float2half_rn(s[ck*8+i][n]);
        *(uint4*)&WT[(size_t)(n0 + n) * K + k0 + ck * 8] = *(uint4*)h;
    }
}

// =================================================================
// Flash attention fp16, BM=128, BN=128 (halved iteration count),
// 256 threads, occ 1, double-buffered K/V, x4/x4.trans frags,
// P in registers. softscale pre-folded into Q.
// =================================================================
#define FST 136
#define FO_Q  0
#define FO_K0 17408
#define FO_K1 34816
#define FO_V0 52224
#define FO_V1 69632
#define FLASH_SMEM (87040 * 2)   // 174080 B

__global__ __launch_bounds__(256, 1) void flash_f16_kernel(
    const __half* __restrict__ Qh, const __half* __restrict__ Kh,
    const __half* __restrict__ Vh, __half* __restrict__ Oh)
{
    extern __shared__ __half fsm[];
    const uint32_t sb = smem_u32(fsm);
    __half* Qs = fsm + FO_Q;

    const int tid  = threadIdx.x;
    const int lane = tid & 31;
    const int w    = tid >> 5;
    const int lg   = lane >> 2;
    const int lc   = lane & 3;
    const int h    = blockIdx.y;
    const int kvh  = h >> 2;
    const int qt   = gridDim.x - 1 - blockIdx.x;   // heavy tiles first
    const int m0   = qt * 128;

    const int ctok = tid >> 4;
    const int cu   = tid & 15;

    const int m_sel = lane >> 3;
    const int r_sel = lane & 7;
    const uint32_t q_lane = sb + (uint32_t)((w * 16 + (m_sel & 1) * 8 + r_sel) * 272
                                            + (m_sel >> 1) * 16);
    const uint32_t k_lane_off = (uint32_t)(((m_sel >> 1) * 8 + r_sel) * 272
                                           + (m_sel & 1) * 16);
    const uint32_t v_lane_off = (uint32_t)(((m_sel & 1) * 8 + r_sel) * 272
                                           + (m_sel >> 1) * 16);

    // ---- prefetch K0/V0 (128 tokens each) ----
    {
        uint32_t kd = sb + FO_K0 * 2;
        uint32_t vd = sb + FO_V0 * 2;
#pragma unroll
        for (int it = 0; it < 8; ++it) {
            int tok = ctok + it * 16;
            cp16(kd + tok * 272 + cu * 16,
                 Kh + ((size_t)tok * NUM_KV + kvh) * HEAD_DIM + cu * 8);
            cp16(vd + tok * 272 + cu * 16,
                 Vh + ((size_t)tok * NUM_KV + kvh) * HEAD_DIM + cu * 8);
        }
        CP_COMMIT();
    }

    // ---- load Q tile ----
#pragma unroll
    for (int it = 0; it < 8; ++it) {
        int id  = tid + it * 256;
        int tok = id >> 4;
        int u   = id & 15;
        *(uint4*)&Qs[tok * FST + u * 8] =
            *(const uint4*)&Qh[((size_t)(m0 + tok) * NUM_HEADS + h) * HEAD_DIM + u * 8];
    }

    float o[16][4];
#pragma unroll
    for (int dt = 0; dt < 16; ++dt)
#pragma unroll
        for (int e = 0; e < 4; ++e) o[dt][e] = 0.f;
    float mrun[2] = {-1e30f, -1e30f};
    float lrun[2] = {0.f, 0.f};

    for (int nt = 0; nt <= qt; ++nt) {
        const int n0 = nt * 128;
        const uint32_t kbuf = sb + (((nt & 1) ? FO_K1 : FO_K0)) * 2;
        const uint32_t vbuf = sb + (((nt & 1) ? FO_V1 : FO_V0)) * 2;

        __syncthreads();   // close iteration nt-1 (its buffers reusable)
        if (nt + 1 <= qt) {
            const int pn0 = (nt + 1) * 128;
            uint32_t kd = sb + ((((nt + 1) & 1) ? FO_K1 : FO_K0)) * 2;
            uint32_t vd = sb + ((((nt + 1) & 1) ? FO_V1 : FO_V0)) * 2;
#pragma unroll
            for (int it = 0; it < 8; ++it) {
                int tok = ctok + it * 16;
                cp16(kd + tok * 272 + cu * 16,
                     Kh + ((size_t)(pn0 + tok) * NUM_KV + kvh) * HEAD_DIM + cu * 8);
                cp16(vd + tok * 272 + cu * 16,
                     Vh + ((size_t)(pn0 + tok) * NUM_KV + kvh) * HEAD_DIM + cu * 8);
            }
        }
        CP_COMMIT();
        CP_WAIT1();
        __syncthreads();   // K/V[nt] visible

        // ---- S = Q K^T : 16 n-tiles, 8 k-steps ----
        float s[16][4];
#pragma unroll
        for (int n = 0; n < 16; ++n)
#pragma unroll
            for (int e = 0; e < 4; ++e) s[n][e] = 0.f;

        const uint32_t k_lane = kbuf + k_lane_off;
#pragma unroll
        for (int ks = 0; ks < 8; ++ks) {
            uint32_t af[4];
            ldsm4(q_lane + ks * 32, af[0], af[1], af[2], af[3]);
#pragma unroll
            for (int np = 0; np < 8; ++np) {
                uint32_t r0, r1, r2, r3;
                ldsm4(k_lane + np * 16 * 272 + ks * 32, r0, r1, r2, r3);
                mma16(s[2*np],   af, r0, r1);
                mma16(s[2*np+1], af, r2, r3);
            }
        }

        // ---- softmax update (softscale pre-folded into Q) ----
        const bool diag = (nt == qt);
        float pmax[2] = {-1e30f, -1e30f};
#pragma unroll
        for (int n = 0; n < 16; ++n) {
#pragma unroll
            for (int e = 0; e < 4; ++e) {
                float v = s[n][e];
                if (diag) {
                    int row = lg + (e >> 1) * 8 + w * 16;   // within tile (m0 == n0)
                    int col = n * 8 + 2 * lc + (e & 1);
                    if (col > row) v = -1e30f;
                }
                s[n][e] = v;
                pmax[e >> 1] = fmaxf(pmax[e >> 1], v);
            }
        }
#pragma unroll
        for (int half = 0; half < 2; ++half) {
            pmax[half] = fmaxf(pmax[half], __shfl_xor_sync(0xffffffffu, pmax[half], 1));
            pmax[half] = fmaxf(pmax[half], __shfl_xor_sync(0xffffffffu, pmax[half], 2));
        }
        float alpha[2];
#pragma unroll
        for (int half = 0; half < 2; ++half) {
            float nm = fmaxf(mrun[half], pmax[half]);
            alpha[half] = __expf(mrun[half] - nm);
            mrun[half] = nm;
            lrun[half] *= alpha[half];
        }
#pragma unroll
        for (int dt = 0; dt < 16; ++dt) {
            o[dt][0] *= alpha[0]; o[dt][1] *= alpha[0];
            o[dt][2] *= alpha[1]; o[dt][3] *= alpha[1];
        }
        uint32_t pf[16][2];
        float lsum[2] = {0.f, 0.f};
#pragma unroll
        for (int n = 0; n < 16; ++n) {
            float p0 = __expf(s[n][0] - mrun[0]);
            float p1 = __expf(s[n][1] - mrun[0]);
            float p2 = __expf(s[n][2] - mrun[1]);
            float p3 = __expf(s[n][3] - mrun[1]);
            lsum[0] += p0 + p1;
            lsum[1] += p2 + p3;
            pf[n][0] = h2bits(__floats2half2_rn(p0, p1));
            pf[n][1] = h2bits(__floats2half2_rn(p2, p3));
        }
#pragma unroll
        for (int half = 0; half < 2; ++half) {
            lsum[half] += __shfl_xor_sync(0xffffffffu, lsum[half], 1);
            lsum[half] += __shfl_xor_sync(0xffffffffu, lsum[half], 2);
            lrun[half] += lsum[half];
        }

        // ---- O += P V : 8 k-steps over 128 kv tokens ----
#pragma unroll
        for (int ks = 0; ks < 8; ++ks) {
            uint32_t af[4];
            af[0] = pf[2*ks][0];
            af[1] = pf[2*ks][1];
            af[2] = pf[2*ks+1][0];
            af[3] = pf[2*ks+1][1];
            uint32_t vbase = vbuf + (uint32_t)(ks * 16) * 272 + v_lane_off;
#pragma unroll
            for (int dtp = 0; dtp < 8; ++dtp) {
                uint32_t r0, r1, r2, r3;
                ldsm4t(vbase + dtp * 32, r0, r1, r2, r3);
                mma16(o[2*dtp],   af, r0, r1);
                mma16(o[2*dtp+1], af, r2, r3);
            }
        }
    }

    // ---- finalize ----
    float inv0 = 1.f / lrun[0];
    float inv1 = 1.f / lrun[1];
#pragma unroll
    for (int dt = 0; dt < 16; ++dt) {
        int row = m0 + w * 16 + lg;
        int col = dt * 8 + 2 * lc;
        *(__half2*)&Oh[((size_t)row * NUM_HEADS + h) * HEAD_DIM + col] =
            __floats2half2_rn(o[dt][0] * inv0, o[dt][1] * inv0);
        *(__half2*)&Oh[((size_t)(row + 8) * NUM_HEADS + h) * HEAD_DIM + col] =
            __floats2half2_rn(o[dt][2] * inv1, o[dt][3] * inv1);
    }
}

// =================================================================
// kernel_launch  (4 launches)
// =================================================================
extern "C" void kernel_launch(void* const* d_in, const int* in_sizes, int n_in,
                              void* d_out, int out_size)
{
    const float* x   = (const float*)d_in[0];
    const int*   pos = (const int*)  d_in[1];
    const float* Wq  = (const float*)d_in[2];
    const float* Wk  = (const float*)d_in[3];
    const float* Wv  = (const float*)d_in[4];
    const float* Wo  = (const float*)d_in[5];
    const float* qsc = (const float*)d_in[6];
    const float* ksc = (const float*)d_in[7];
    float* out = (float*)d_out;

    __half *gqh, *gkh, *gvh, *gctxh, *gxh, *gwqkvT, *gwoT;
    float* grope;
    cudaGetSymbolAddress((void**)&gqh,    g_qh);
    cudaGetSymbolAddress((void**)&gkh,    g_kh);
    cudaGetSymbolAddress((void**)&gvh,    g_vh);
    cudaGetSymbolAddress((void**)&gctxh,  g_ctxh);
    cudaGetSymbolAddress((void**)&gxh,    g_xh);
    cudaGetSymbolAddress((void**)&gwqkvT, g_wqkvT);
    cudaGetSymbolAddress((void**)&gwoT,   g_woT);
    cudaGetSymbolAddress((void**)&grope,  g_rope);

    const int NQ = NUM_HEADS * HEAD_DIM;   // 4096

    cudaFuncSetAttribute(gemm_f16<0>,
                         cudaFuncAttributeMaxDynamicSharedMemorySize, GEMM_SMEM);
    cudaFuncSetAttribute(gemm_f16<1>,
                         cudaFuncAttributeMaxDynamicSharedMemorySize, GEMM_SMEM);
    cudaFuncSetAttribute(flash_f16_kernel,
                         cudaFuncAttributeMaxDynamicSharedMemorySize, FLASH_SMEM);

    // [0] merged pre-pass: transposes + x->fp16 + rope table
    prepass_all_kernel<<<11776, 256>>>(Wq, Wk, Wv, Wo, x, pos,
                                       gwqkvT, gwoT, gxh, grope);
    // [1] fused QKV projection + RMSNorm + RoPE (+softscale fold)
    gemm_f16<1><<<dim3(6144 / 128, SEQ / 128), 256, GEMM_SMEM>>>(
        gxh, gwqkvT, nullptr, gqh, gkh, gvh, qsc, ksc, grope, 6144, D_IN);
    // [2] flash attention (BN=128)
    flash_f16_kernel<<<dim3(SEQ / 128, NUM_HEADS), 256, FLASH_SMEM>>>(
        gqh, gkh, gvh, gctxh);
    // [3] output projection
    gemm_f16<0><<<dim3(D_IN / 128, SEQ / 128), 256, GEMM_SMEM>>>(
        gctxh, gwoT, out, nullptr, nullptr, nullptr, nullptr, nullptr, nullptr,
        D_IN, NQ);
}

// round 15
// speedup vs baseline: 1.0600x; 1.0075x over previous
#include <cuda_runtime.h>
#include <cuda_fp16.h>
#include <math.h>
#include <stdint.h>

#define D_IN       4096
#define NUM_HEADS  32
#define HEAD_DIM   128
#define NUM_KV     8
#define SEQ        2048

// -------- scratch (device globals; no allocation allowed) --------
__device__ __half g_qh [(size_t)SEQ * NUM_HEADS * HEAD_DIM];
__device__ __half g_kh [(size_t)SEQ * NUM_KV   * HEAD_DIM];
__device__ __half g_vh [(size_t)SEQ * NUM_KV   * HEAD_DIM];
__device__ __half g_ctxh[(size_t)SEQ * NUM_HEADS * HEAD_DIM];
__device__ __half g_xh [(size_t)SEQ * D_IN];
__device__ __half g_wqkvT[(size_t)6144 * D_IN];                 // [N][K] fp16
__device__ __half g_woT[(size_t)D_IN * (NUM_HEADS*HEAD_DIM)];   // [N][K]
__device__ float  g_rope[(size_t)SEQ * 64 * 2];                 // [tok][f]{cos,sin}

// ---------------- helpers ----------------
__device__ __forceinline__ uint32_t smem_u32(const void* p) {
    uint32_t a;
    asm("{ .reg .u64 t; cvta.to.shared.u64 t, %1; cvt.u32.u64 %0, t; }"
        : "=r"(a) : "l"(p));
    return a;
}
__device__ __forceinline__ void cp16(uint32_t d, const void* s) {
    asm volatile("cp.async.cg.shared.global [%0], [%1], 16;"
                 :: "r"(d), "l"(s) : "memory");
}
#define CP_COMMIT() asm volatile("cp.async.commit_group;" ::: "memory")
#define CP_WAIT1()  asm volatile("cp.async.wait_group 1;" ::: "memory")

__device__ __forceinline__ void mma16(float* c, const uint32_t* a,
                                      uint32_t b0, uint32_t b1) {
    asm volatile(
        "mma.sync.aligned.m16n8k16.row.col.f32.f16.f16.f32 "
        "{%0,%1,%2,%3},{%4,%5,%6,%7},{%8,%9},{%0,%1,%2,%3};\n"
        : "+f"(c[0]), "+f"(c[1]), "+f"(c[2]), "+f"(c[3])
        : "r"(a[0]), "r"(a[1]), "r"(a[2]), "r"(a[3]), "r"(b0), "r"(b1));
}
__device__ __forceinline__ void ldsm4(uint32_t addr, uint32_t& r0, uint32_t& r1,
                                      uint32_t& r2, uint32_t& r3) {
    asm volatile("ldmatrix.sync.aligned.m8n8.x4.shared.b16 {%0,%1,%2,%3}, [%4];"
                 : "=r"(r0), "=r"(r1), "=r"(r2), "=r"(r3) : "r"(addr));
}
__device__ __forceinline__ void ldsm4t(uint32_t addr, uint32_t& r0, uint32_t& r1,
                                       uint32_t& r2, uint32_t& r3) {
    asm volatile("ldmatrix.sync.aligned.m8n8.x4.trans.shared.b16 {%0,%1,%2,%3}, [%4];"
                 : "=r"(r0), "=r"(r1), "=r"(r2), "=r"(r3) : "r"(addr));
}
__device__ __forceinline__ uint32_t h2bits(__half2 h) {
    return *(uint32_t*)&h;
}

// =================================================================
// fp16 GEMM (best measured config — at f32-acc HMMA hw ceiling):
// B transposed [N][K]. BM=BN=128, BK=64, 256 thr (8 warps: 4M x 2N),
// 3-stage cp.async, ldsm4 frags, smem stride 72 halves, 2 CTAs/SM.
// MODE 0: fp32 out. MODE 1: fused QKV epilogue (RMSNorm+RoPE),
// softscale folded into Q's row scale.
// =================================================================
#define GSTAGE_BYTES 36864
#define GEMM_SMEM (3 * GSTAGE_BYTES)

template<int MODE>
__global__ __launch_bounds__(256, 2) void gemm_f16(
    const __half* __restrict__ A, const __half* __restrict__ B,
    float* __restrict__ Cout,
    __half* __restrict__ Qout, __half* __restrict__ Kout, __half* __restrict__ Vout,
    const float* __restrict__ qsc, const float* __restrict__ ksc,
    const float* __restrict__ ropeT,
    int N, int K)
{
    extern __shared__ __half sh[];
    const uint32_t sb = smem_u32(sh);
    const int tid = threadIdx.x;
    const int lane = tid & 31, wid = tid >> 5;
    const int wm = wid & 3, wn = wid >> 2;
    const int lg = lane >> 2, lc = lane & 3;
    const int m0 = blockIdx.y * 128, n0 = blockIdx.x * 128;
    const int nsteps = K / 64;
    const int lrow = tid >> 3;
    const int lchk = tid & 7;

    const uint32_t a_off = (uint32_t)((wm * 32 + (lane & 15)) * 144 + (lane >> 4) * 16);
    const uint32_t b_off = (uint32_t)(18432 +
        (wn * 64 + (lane & 7) + ((lane >> 4) * 8)) * 144 + ((lane >> 3) & 1) * 16);

    float acc[2][8][4];
#pragma unroll
    for (int i = 0; i < 2; ++i)
#pragma unroll
        for (int j = 0; j < 8; ++j)
#pragma unroll
            for (int e = 0; e < 4; ++e) acc[i][j][e] = 0.f;

    const __half* Ag = A + (size_t)m0 * K;
    const __half* Bg = B + (size_t)n0 * K;

#define LOAD_STAGE(s, k0) do {                                            \
    uint32_t as_ = sb + (uint32_t)(s) * GSTAGE_BYTES;                     \
    uint32_t bs_ = as_ + 18432;                                           \
    _Pragma("unroll")                                                     \
    for (int j_ = 0; j_ < 4; ++j_) {                                      \
        int row_ = lrow + 32 * j_;                                        \
        cp16(as_ + row_ * 144 + lchk * 16,                                \
             Ag + (size_t)row_ * K + (k0) + lchk * 8);                    \
        cp16(bs_ + row_ * 144 + lchk * 16,                                \
             Bg + (size_t)row_ * K + (k0) + lchk * 8);                    \
    }                                                                     \
} while (0)

    LOAD_STAGE(0, 0);  CP_COMMIT();
    LOAD_STAGE(1, 64); CP_COMMIT();

    for (int s = 0; s < nsteps; ++s) {
        CP_WAIT1();
        __syncthreads();
        if (s + 2 < nsteps) {
            int sn = s + 2; int bufn = sn - (sn / 3) * 3;
            LOAD_STAGE(bufn, sn * 64);
        }
        CP_COMMIT();

        const int buf = s - (s / 3) * 3;
        const uint32_t st = sb + (uint32_t)buf * GSTAGE_BYTES;
#pragma unroll
        for (int ks = 0; ks < 4; ++ks) {
            uint32_t af[2][4];
            ldsm4(st + a_off + ks * 32,            af[0][0], af[0][1], af[0][2], af[0][3]);
            ldsm4(st + a_off + ks * 32 + 16 * 144, af[1][0], af[1][1], af[1][2], af[1][3]);
            uint32_t bf[8][2];
#pragma unroll
            for (int ntp = 0; ntp < 4; ++ntp) {
                uint32_t r0, r1, r2, r3;
                ldsm4(st + b_off + ks * 32 + ntp * 16 * 144, r0, r1, r2, r3);
                bf[2*ntp][0] = r0; bf[2*ntp][1] = r1;
                bf[2*ntp+1][0] = r2; bf[2*ntp+1][1] = r3;
            }
#pragma unroll
            for (int nt = 0; nt < 8; ++nt) {
                mma16(acc[0][nt], af[0], bf[nt][0], bf[nt][1]);
                mma16(acc[1][nt], af[1], bf[nt][0], bf[nt][1]);
            }
        }
    }
#undef LOAD_STAGE

    if (MODE == 0) {
#pragma unroll
        for (int mt = 0; mt < 2; ++mt)
#pragma unroll
            for (int nt = 0; nt < 8; ++nt) {
                int row = m0 + wm * 32 + mt * 16 + lg;
                int col = n0 + wn * 64 + nt * 8 + 2 * lc;
                *(float2*)&Cout[(size_t)row * N + col] =
                    make_float2(acc[mt][nt][0], acc[mt][nt][1]);
                *(float2*)&Cout[(size_t)(row + 8) * N + col] =
                    make_float2(acc[mt][nt][2], acc[mt][nt][3]);
            }
        return;
    }

    // ---------------- MODE 1: fused QKV epilogue ----------------
    if (n0 >= 5120) {
#pragma unroll
        for (int mt = 0; mt < 2; ++mt)
#pragma unroll
            for (int nt = 0; nt < 8; ++nt) {
                int row = m0 + wm * 32 + mt * 16 + lg;
                int col = n0 - 5120 + wn * 64 + nt * 8 + 2 * lc;
                *(__half2*)&Vout[(size_t)row * 1024 + col] =
                    __floats2half2_rn(acc[mt][nt][0], acc[mt][nt][1]);
                *(__half2*)&Vout[(size_t)(row + 8) * 1024 + col] =
                    __floats2half2_rn(acc[mt][nt][2], acc[mt][nt][3]);
            }
        return;
    }

    const bool isQ = (n0 < 4096);
    const float* sc = isQ ? qsc : ksc;
    const float postmul = isQ ? 0.08838834764831845f : 1.0f;  // softscale fold
    float* ssb = (float*)sh;          // [2][128]
    float* epi = (float*)sh + 256;    // [128][132]

    __syncthreads();

#pragma unroll
    for (int mt = 0; mt < 2; ++mt) {
        float s0 = 0.f, s1 = 0.f;
#pragma unroll
        for (int nt = 0; nt < 8; ++nt) {
            s0 += acc[mt][nt][0]*acc[mt][nt][0] + acc[mt][nt][1]*acc[mt][nt][1];
            s1 += acc[mt][nt][2]*acc[mt][nt][2] + acc[mt][nt][3]*acc[mt][nt][3];
        }
        s0 += __shfl_xor_sync(0xffffffffu, s0, 1);
        s0 += __shfl_xor_sync(0xffffffffu, s0, 2);
        s1 += __shfl_xor_sync(0xffffffffu, s1, 1);
        s1 += __shfl_xor_sync(0xffffffffu, s1, 2);
        if (lc == 0) {
            int r = wm * 32 + mt * 16 + lg;
            ssb[wn * 128 + r]     = s0;
            ssb[wn * 128 + r + 8] = s1;
        }
    }
    __syncthreads();

#pragma unroll
    for (int mt = 0; mt < 2; ++mt) {
        int r0 = wm * 32 + mt * 16 + lg;
        float rs0 = rsqrtf((ssb[r0]     + ssb[128 + r0])     * (1.f/128.f) + 1e-6f) * postmul;
        float rs1 = rsqrtf((ssb[r0 + 8] + ssb[128 + r0 + 8]) * (1.f/128.f) + 1e-6f) * postmul;
#pragma unroll
        for (int nt = 0; nt < 8; ++nt) {
            int c0 = wn * 64 + nt * 8 + 2 * lc;
            float2 scv = *(const float2*)&sc[c0];
            *(float2*)&epi[r0 * 132 + c0] =
                make_float2(acc[mt][nt][0] * rs0 * scv.x, acc[mt][nt][1] * rs0 * scv.y);
            *(float2*)&epi[(r0 + 8) * 132 + c0] =
                make_float2(acc[mt][nt][2] * rs1 * scv.x, acc[mt][nt][3] * rs1 * scv.y);
        }
    }
    __syncthreads();

    const int head = isQ ? (n0 >> 7) : ((n0 - 4096) >> 7);
    const int hstride = isQ ? NUM_HEADS : NUM_KV;
    __half* outp = isQ ? Qout : Kout;
#pragma unroll
    for (int mt = 0; mt < 2; ++mt) {
#pragma unroll
        for (int nt = 0; nt < 8; ++nt) {
            int r0 = wm * 32 + mt * 16 + lg;
            int c0 = wn * 64 + nt * 8 + 2 * lc;
            int cf = c0 & 63;
            float sgn = (c0 < 64) ? -1.f : 1.f;
#pragma unroll
            for (int hr = 0; hr < 2; ++hr) {
                int r = r0 + hr * 8;
                int tok = m0 + r;
                float4 tb = *(const float4*)&ropeT[(size_t)(tok * 64 + cf) * 2];
                float2 v = *(const float2*)&epi[r * 132 + c0];
                float2 p = *(const float2*)&epi[r * 132 + (c0 ^ 64)];
                float o0 = fmaf(v.x, tb.x, sgn * p.x * tb.y);
                float o1 = fmaf(v.y, tb.z, sgn * p.y * tb.w);
                *(__half2*)&outp[((size_t)tok * hstride + head) * 128 + c0] =
                    __floats2half2_rn(o0, o1);
            }
        }
    }
}

// =================================================================
// merged pre-pass (unchanged)
// =================================================================
__global__ __launch_bounds__(256) void prepass_all_kernel(
    const float* __restrict__ Wq, const float* __restrict__ Wk,
    const float* __restrict__ Wv, const float* __restrict__ Wo,
    const float* __restrict__ x, const int* __restrict__ positions,
    __half* __restrict__ wqkvT, __half* __restrict__ woT,
    __half* __restrict__ xh, float* __restrict__ ropeT)
{
    const int tid = threadIdx.x;
    int b = blockIdx.x;

    if (b >= 11264) {
        int idx = (b - 11264) * 256 + tid;
        int tok = idx >> 6, f = idx & 63;
        double invf = exp2(-(double)f * (13.287712379549449 / 64.0));
        double ang  = (double)positions[tok] * invf;
        const double twopi = 6.283185307179586476925287;
        ang -= twopi * floor(ang / twopi);
        float c, s;
        sincosf((float)ang, &s, &c);
        ropeT[(size_t)idx * 2]     = c;
        ropeT[(size_t)idx * 2 + 1] = s;
        return;
    }
    if (b >= 10240) {
        const int n4 = (SEQ * D_IN) / 4;
        int i = (b - 10240) * 256 + tid;
        const int stride = 1024 * 256;
        for (; i < n4; i += stride) {
            float4 v = ((const float4*)x)[i];
            __half2 h0 = __floats2half2_rn(v.x, v.y);
            __half2 h1 = __floats2half2_rn(v.z, v.w);
            ((uint2*)xh)[i] = make_uint2(h2bits(h0), h2bits(h1));
        }
        return;
    }

    __shared__ float s[64][65];
    const float* W;
    __half* WT;
    int K, N, bx, by;
    if (b < 4096) {
        W = Wq; WT = wqkvT; K = D_IN; N = 4096;
        bx = b & 63; by = b >> 6;
    } else if (b < 5120) {
        b -= 4096;
        W = Wk; WT = wqkvT + (size_t)4096 * D_IN; K = D_IN; N = 1024;
        bx = b & 15; by = b >> 4;
    } else if (b < 6144) {
        b -= 5120;
        W = Wv; WT = wqkvT + (size_t)5120 * D_IN; K = D_IN; N = 1024;
        bx = b & 15; by = b >> 4;
    } else {
        b -= 6144;
        W = Wo; WT = woT; K = 4096; N = D_IN;
        bx = b & 63; by = b >> 6;
    }
    const int k0 = by * 64;
    const int n0 = bx * 64;
    const int rk = tid >> 4;
    const int cn = tid & 15;
#pragma unroll
    for (int it = 0; it < 4; ++it) {
        int k = rk + it * 16;
        float4 v = *(const float4*)&W[(size_t)(k0 + k) * N + n0 + cn * 4];
        s[k][cn*4+0] = v.x; s[k][cn*4+1] = v.y;
        s[k][cn*4+2] = v.z; s[k][cn*4+3] = v.w;
    }
    __syncthreads();
    const int rn = tid >> 3;
    const int ck = tid & 7;
#pragma unroll
    for (int it = 0; it < 2; ++it) {
        int n = rn + it * 32;
        __half h[8];
#pragma unroll
        for (int i = 0; i < 8; ++i) h[i] = __float2half_rn(s[ck*8+i][n]);
        *(uint4*)&WT[(size_t)(n0 + n) * K + k0 + ck * 8] = *(uint4*)h;
    }
}

// =================================================================
// Flash attention fp16, BM=BN=128, 256 thr, occ 1.
// Q now cp.async'd in group 0 alongside K0/V0.
// =================================================================
#define FST 136
#define FO_Q  0
#define FO_K0 17408
#define FO_K1 34816
#define FO_V0 52224
#define FO_V1 69632
#define FLASH_SMEM (87040 * 2)   // 174080 B

__global__ __launch_bounds__(256, 1) void flash_f16_kernel(
    const __half* __restrict__ Qh, const __half* __restrict__ Kh,
    const __half* __restrict__ Vh, __half* __restrict__ Oh)
{
    extern __shared__ __half fsm[];
    const uint32_t sb = smem_u32(fsm);

    const int tid  = threadIdx.x;
    const int lane = tid & 31;
    const int w    = tid >> 5;
    const int lg   = lane >> 2;
    const int lc   = lane & 3;
    const int h    = blockIdx.y;
    const int kvh  = h >> 2;
    const int qt   = gridDim.x - 1 - blockIdx.x;   // heavy tiles first
    const int m0   = qt * 128;

    const int ctok = tid >> 4;
    const int cu   = tid & 15;

    const int m_sel = lane >> 3;
    const int r_sel = lane & 7;
    const uint32_t q_lane = sb + (uint32_t)((w * 16 + (m_sel & 1) * 8 + r_sel) * 272
                                            + (m_sel >> 1) * 16);
    const uint32_t k_lane_off = (uint32_t)(((m_sel >> 1) * 8 + r_sel) * 272
                                           + (m_sel & 1) * 16);
    const uint32_t v_lane_off = (uint32_t)(((m_sel & 1) * 8 + r_sel) * 272
                                           + (m_sel >> 1) * 16);

    // ---- prefetch Q + K0 + V0 in one cp.async group ----
    {
        uint32_t qd = sb + FO_Q  * 2;
        uint32_t kd = sb + FO_K0 * 2;
        uint32_t vd = sb + FO_V0 * 2;
#pragma unroll
        for (int it = 0; it < 8; ++it) {
            int tok = ctok + it * 16;
            cp16(qd + tok * 272 + cu * 16,
                 Qh + ((size_t)(m0 + tok) * NUM_HEADS + h) * HEAD_DIM + cu * 8);
            cp16(kd + tok * 272 + cu * 16,
                 Kh + ((size_t)tok * NUM_KV + kvh) * HEAD_DIM + cu * 8);
            cp16(vd + tok * 272 + cu * 16,
                 Vh + ((size_t)tok * NUM_KV + kvh) * HEAD_DIM + cu * 8);
        }
        CP_COMMIT();
    }

    float o[16][4];
#pragma unroll
    for (int dt = 0; dt < 16; ++dt)
#pragma unroll
        for (int e = 0; e < 4; ++e) o[dt][e] = 0.f;
    float mrun[2] = {-1e30f, -1e30f};
    float lrun[2] = {0.f, 0.f};

    for (int nt = 0; nt <= qt; ++nt) {
        const uint32_t kbuf = sb + (((nt & 1) ? FO_K1 : FO_K0)) * 2;
        const uint32_t vbuf = sb + (((nt & 1) ? FO_V1 : FO_V0)) * 2;

        __syncthreads();   // close iteration nt-1 (its buffers reusable)
        if (nt + 1 <= qt) {
            const int pn0 = (nt + 1) * 128;
            uint32_t kd = sb + ((((nt + 1) & 1) ? FO_K1 : FO_K0)) * 2;
            uint32_t vd = sb + ((((nt + 1) & 1) ? FO_V1 : FO_V0)) * 2;
#pragma unroll
            for (int it = 0; it < 8; ++it) {
                int tok = ctok + it * 16;
                cp16(kd + tok * 272 + cu * 16,
                     Kh + ((size_t)(pn0 + tok) * NUM_KV + kvh) * HEAD_DIM + cu * 8);
                cp16(vd + tok * 272 + cu * 16,
                     Vh + ((size_t)(pn0 + tok) * NUM_KV + kvh) * HEAD_DIM + cu * 8);
            }
        }
        CP_COMMIT();
        CP_WAIT1();
        __syncthreads();   // Q (first iter) and K/V[nt] visible

        // ---- S = Q K^T : 16 n-tiles, 8 k-steps ----
        float s[16][4];
#pragma unroll
        for (int n = 0; n < 16; ++n)
#pragma unroll
            for (int e = 0; e < 4; ++e) s[n][e] = 0.f;

        const uint32_t k_lane = kbuf + k_lane_off;
#pragma unroll
        for (int ks = 0; ks < 8; ++ks) {
            uint32_t af[4];
            ldsm4(q_lane + ks * 32, af[0], af[1], af[2], af[3]);
#pragma unroll
            for (int np = 0; np < 8; ++np) {
                uint32_t r0, r1, r2, r3;
                ldsm4(k_lane + np * 16 * 272 + ks * 32, r0, r1, r2, r3);
                mma16(s[2*np],   af, r0, r1);
                mma16(s[2*np+1], af, r2, r3);
            }
        }

        // ---- softmax update (softscale pre-folded into Q) ----
        const bool diag = (nt == qt);
        float pmax[2] = {-1e30f, -1e30f};
#pragma unroll
        for (int n = 0; n < 16; ++n) {
#pragma unroll
            for (int e = 0; e < 4; ++e) {
                float v = s[n][e];
                if (diag) {
                    int row = lg + (e >> 1) * 8 + w * 16;
                    int col = n * 8 + 2 * lc + (e & 1);
                    if (col > row) v = -1e30f;
                }
                s[n][e] = v;
                pmax[e >> 1] = fmaxf(pmax[e >> 1], v);
            }
        }
#pragma unroll
        for (int half = 0; half < 2; ++half) {
            pmax[half] = fmaxf(pmax[half], __shfl_xor_sync(0xffffffffu, pmax[half], 1));
            pmax[half] = fmaxf(pmax[half], __shfl_xor_sync(0xffffffffu, pmax[half], 2));
        }
        float alpha[2];
#pragma unroll
        for (int half = 0; half < 2; ++half) {
            float nm = fmaxf(mrun[half], pmax[half]);
            alpha[half] = __expf(mrun[half] - nm);
            mrun[half] = nm;
            lrun[half] *= alpha[half];
        }
#pragma unroll
        for (int dt = 0; dt < 16; ++dt) {
            o[dt][0] *= alpha[0]; o[dt][1] *= alpha[0];
            o[dt][2] *= alpha[1]; o[dt][3] *= alpha[1];
        }
        uint32_t pf[16][2];
        float lsum[2] = {0.f, 0.f};
#pragma unroll
        for (int n = 0; n < 16; ++n) {
            float p0 = __expf(s[n][0] - mrun[0]);
            float p1 = __expf(s[n][1] - mrun[0]);
            float p2 = __expf(s[n][2] - mrun[1]);
            float p3 = __expf(s[n][3] - mrun[1]);
            lsum[0] += p0 + p1;
            lsum[1] += p2 + p3;
            pf[n][0] = h2bits(__floats2half2_rn(p0, p1));
            pf[n][1] = h2bits(__floats2half2_rn(p2, p3));
        }
#pragma unroll
        for (int half = 0; half < 2; ++half) {
            lsum[half] += __shfl_xor_sync(0xffffffffu, lsum[half], 1);
            lsum[half] += __shfl_xor_sync(0xffffffffu, lsum[half], 2);
            lrun[half] += lsum[half];
        }

        // ---- O += P V : 8 k-steps over 128 kv tokens ----
#pragma unroll
        for (int ks = 0; ks < 8; ++ks) {
            uint32_t af[4];
            af[0] = pf[2*ks][0];
            af[1] = pf[2*ks][1];
            af[2] = pf[2*ks+1][0];
            af[3] = pf[2*ks+1][1];
            uint32_t vbase = vbuf + (uint32_t)(ks * 16) * 272 + v_lane_off;
#pragma unroll
            for (int dtp = 0; dtp < 8; ++dtp) {
                uint32_t r0, r1, r2, r3;
                ldsm4t(vbase + dtp * 32, r0, r1, r2, r3);
                mma16(o[2*dtp],   af, r0, r1);
                mma16(o[2*dtp+1], af, r2, r3);
            }
        }
    }

    // ---- finalize ----
    float inv0 = 1.f / lrun[0];
    float inv1 = 1.f / lrun[1];
#pragma unroll
    for (int dt = 0; dt < 16; ++dt) {
        int row = m0 + w * 16 + lg;
        int col = dt * 8 + 2 * lc;
        *(__half2*)&Oh[((size_t)row * NUM_HEADS + h) * HEAD_DIM + col] =
            __floats2half2_rn(o[dt][0] * inv0, o[dt][1] * inv0);
        *(__half2*)&Oh[((size_t)(row + 8) * NUM_HEADS + h) * HEAD_DIM + col] =
            __floats2half2_rn(o[dt][2] * inv1, o[dt][3] * inv1);
    }
}

// =================================================================
// kernel_launch  (4 launches)
// =================================================================
extern "C" void kernel_launch(void* const* d_in, const int* in_sizes, int n_in,
                              void* d_out, int out_size)
{
    const float* x   = (const float*)d_in[0];
    const int*   pos = (const int*)  d_in[1];
    const float* Wq  = (const float*)d_in[2];
    const float* Wk  = (const float*)d_in[3];
    const float* Wv  = (const float*)d_in[4];
    const float* Wo  = (const float*)d_in[5];
    const float* qsc = (const float*)d_in[6];
    const float* ksc = (const float*)d_in[7];
    float* out = (float*)d_out;

    __half *gqh, *gkh, *gvh, *gctxh, *gxh, *gwqkvT, *gwoT;
    float* grope;
    cudaGetSymbolAddress((void**)&gqh,    g_qh);
    cudaGetSymbolAddress((void**)&gkh,    g_kh);
    cudaGetSymbolAddress((void**)&gvh,    g_vh);
    cudaGetSymbolAddress((void**)&gctxh,  g_ctxh);
    cudaGetSymbolAddress((void**)&gxh,    g_xh);
    cudaGetSymbolAddress((void**)&gwqkvT, g_wqkvT);
    cudaGetSymbolAddress((void**)&gwoT,   g_woT);
    cudaGetSymbolAddress((void**)&grope,  g_rope);

    const int NQ = NUM_HEADS * HEAD_DIM;   // 4096

    cudaFuncSetAttribute(gemm_f16<0>,
                         cudaFuncAttributeMaxDynamicSharedMemorySize, GEMM_SMEM);
    cudaFuncSetAttribute(gemm_f16<1>,
                         cudaFuncAttributeMaxDynamicSharedMemorySize, GEMM_SMEM);
    cudaFuncSetAttribute(flash_f16_kernel,
                         cudaFuncAttributeMaxDynamicSharedMemorySize, FLASH_SMEM);

    // [0] merged pre-pass: transposes + x->fp16 + rope table
    prepass_all_kernel<<<11776, 256>>>(Wq, Wk, Wv, Wo, x, pos,
                                       gwqkvT, gwoT, gxh, grope);
    // [1] fused QKV projection + RMSNorm + RoPE (+softscale fold)
    gemm_f16<1><<<dim3(6144 / 128, SEQ / 128), 256, GEMM_SMEM>>>(
        gxh, gwqkvT, nullptr, gqh, gkh, gvh, qsc, ksc, grope, 6144, D_IN);
    // [2] flash attention (BN=128, Q via cp.async)
    flash_f16_kernel<<<dim3(SEQ / 128, NUM_HEADS), 256, FLASH_SMEM>>>(
        gqh, gkh, gvh, gctxh);
    // [3] output projection
    gemm_f16<0><<<dim3(D_IN / 128, SEQ / 128), 256, GEMM_SMEM>>>(
        gctxh, gwoT, out, nullptr, nullptr, nullptr, nullptr, nullptr, nullptr,
        D_IN, NQ);
}